// round 5
// baseline (speedup 1.0000x reference)
#include <cuda_runtime.h>
#include <cuda_bf16.h>
#include <cstdint>

// Problem constants (B=4, Q=256, K=1024, H=128)
#define BB 4
#define QQ 256
#define KK 1024
#define HH 128
#define QT 4            // queries per score block
#define KS 2            // k-splits per query row
#define KHALF (KK / KS) // 512
#define T2 32           // k-rows per stage tile
#define P4 33           // float4 pitch of kp tile row
#define QT3 8           // queries per softmax/ctx block

// Scratch for projections (device globals — no allocation allowed)
__device__ float g_qp[BB * QQ * HH];   // 512 KB
__device__ float g_kp[BB * KK * HH];   // 2 MB

__device__ __forceinline__ float fast_tanh(float x) {
    float y;
    asm("tanh.approx.f32 %0, %1;" : "=f"(y) : "f"(x));
    return y;
}

__device__ __forceinline__ void cp_async16(void* dst, const void* src) {
    uint32_t d = (uint32_t)__cvta_generic_to_shared(dst);
    asm volatile("cp.async.ca.shared.global [%0], [%1], 16;\n" :: "r"(d), "l"(src));
}

// ---------------- Fused projection GEMM: out[row][h] = sum_d in[row][d] * W[h][d]
__global__ __launch_bounds__(256) void proj_kernel(
    const float* __restrict__ query, const float* __restrict__ key,
    const float* __restrict__ Wq, const float* __restrict__ Wk) {
    __shared__ float s_a[64 * 36];
    __shared__ float s_b[64 * 36];

    int bx = blockIdx.x;
    const float* in; const float* W; float* out;
    int rowTile, hTile;
    if (bx < 32) { in = query; W = Wq; out = g_qp; rowTile = (bx >> 1) * 64; hTile = (bx & 1) * 64; }
    else { bx -= 32; in = key; W = Wk; out = g_kp; rowTile = (bx >> 1) * 64; hTile = (bx & 1) * 64; }

    const int tid = threadIdx.x;
    const int tx = tid & 15;
    const int ty = tid >> 4;

    float acc[4][4] = {};

    for (int kc = 0; kc < 4; ++kc) {
        __syncthreads();
        {
            int idx = tid;
#pragma unroll
            for (int i = 0; i < 2; ++i, idx += 256) {
                int r = idx >> 3, c = idx & 7;
                float4 va = ((const float4*)(in + (size_t)(rowTile + r) * HH + kc * 32))[c];
                ((float4*)s_a)[r * 9 + c] = va;
                float4 vb = ((const float4*)(W + (size_t)(hTile + r) * HH + kc * 32))[c];
                ((float4*)s_b)[r * 9 + c] = vb;
            }
        }
        __syncthreads();

#pragma unroll
        for (int s = 0; s < 8; ++s) {
            float4 a[4], b[4];
#pragma unroll
            for (int i = 0; i < 4; ++i) a[i] = ((const float4*)s_a)[(ty + 16 * i) * 9 + s];
#pragma unroll
            for (int j = 0; j < 4; ++j) b[j] = ((const float4*)s_b)[(tx + 16 * j) * 9 + s];
#pragma unroll
            for (int i = 0; i < 4; ++i)
#pragma unroll
                for (int j = 0; j < 4; ++j)
                    acc[i][j] += a[i].x * b[j].x + a[i].y * b[j].y
                               + a[i].z * b[j].z + a[i].w * b[j].w;
        }
    }

#pragma unroll
    for (int i = 0; i < 4; ++i)
#pragma unroll
        for (int j = 0; j < 4; ++j)
            out[(size_t)(rowTile + ty + 16 * i) * HH + hTile + tx + 16 * j] = acc[i][j];
}

// ---------------- Score kernel: masked raw scores -> out_aw (scratch).
// grid 512: bx = b*128 + qt*2 + ks. Block 256 thr, 8 warps: q = w&3, kh = w>>2.
// Thread: hs = lane>>2 (h-slice of 16 floats), ksub = lane&3.
__global__ __launch_bounds__(256, 3) void score_kernel(const int* __restrict__ mask,
                                                       const float* __restrict__ vvec,
                                                       float* __restrict__ out_aw) {
    __shared__ float4 s_kp[2][T2 * P4];

    const int tid = threadIdx.x;
    const int bx = blockIdx.x;
    const int b = bx >> 7;
    const int qt = (bx >> 1) & 63;
    const int ks = bx & 1;
    const int q0 = qt * QT;
    const int kbase = ks * KHALF;
    const int warp = tid >> 5;
    const int lane = tid & 31;
    const int q = warp & 3;
    const int kh = warp >> 2;
    const int hs = lane >> 2;
    const int ksub = lane & 3;

    const float4* kp4 = (const float4*)g_kp + ((size_t)b * KK + kbase) * (HH / 4);

    float4 qq[4], vv[4];
    {
        const float4* qp = (const float4*)g_qp + (size_t)(b * QQ + q0 + q) * (HH / 4) + hs * 4;
        const float4* v4 = (const float4*)vvec + hs * 4;
#pragma unroll
        for (int i = 0; i < 4; ++i) { qq[i] = qp[i]; vv[i] = v4[i]; }
    }

    const int bq = b * QQ + q0 + q;
    const int* mrow = mask + (size_t)bq * KK;
    float* aw = out_aw + (size_t)bq * KK;

    auto stage = [&](int t, int buf) {
        const float4* src = kp4 + (size_t)t * T2 * (HH / 4);
        float4* dst = &s_kp[buf][0];
#pragma unroll
        for (int i = 0; i < 4; ++i) {
            int idx = tid + i * 256;              // 0..1023
            int r = idx >> 5, c = idx & 31;
            cp_async16(dst + r * P4 + c, src + idx);
        }
        asm volatile("cp.async.commit_group;\n");
    };

    stage(0, 0);
    for (int t = 0; t < KHALF / T2; ++t) {
        const int buf = t & 1;
        if (t < KHALF / T2 - 1) {
            stage(t + 1, buf ^ 1);
            asm volatile("cp.async.wait_group 1;\n");
        } else {
            asm volatile("cp.async.wait_group 0;\n");
        }
        __syncthreads();

        const float4* base = &s_kp[buf][0] + hs * 4;
#pragma unroll
        for (int it = 0; it < 4; ++it) {
            const int kk = kh * 16 + it * 4 + ksub;
            const float4* kr = base + kk * P4;
            float4 k0v = kr[0], k1v = kr[1], k2v = kr[2], k3v = kr[3];
            float a0 = 0.f, a1 = 0.f;
            a0 += vv[0].x * fast_tanh(qq[0].x + k0v.x);
            a0 += vv[0].y * fast_tanh(qq[0].y + k0v.y);
            a0 += vv[0].z * fast_tanh(qq[0].z + k0v.z);
            a0 += vv[0].w * fast_tanh(qq[0].w + k0v.w);
            a1 += vv[1].x * fast_tanh(qq[1].x + k1v.x);
            a1 += vv[1].y * fast_tanh(qq[1].y + k1v.y);
            a1 += vv[1].z * fast_tanh(qq[1].z + k1v.z);
            a1 += vv[1].w * fast_tanh(qq[1].w + k1v.w);
            a0 += vv[2].x * fast_tanh(qq[2].x + k2v.x);
            a0 += vv[2].y * fast_tanh(qq[2].y + k2v.y);
            a0 += vv[2].z * fast_tanh(qq[2].z + k2v.z);
            a0 += vv[2].w * fast_tanh(qq[2].w + k2v.w);
            a1 += vv[3].x * fast_tanh(qq[3].x + k3v.x);
            a1 += vv[3].y * fast_tanh(qq[3].y + k3v.y);
            a1 += vv[3].z * fast_tanh(qq[3].z + k3v.z);
            a1 += vv[3].w * fast_tanh(qq[3].w + k3v.w);
            float acc = a0 + a1;
            acc += __shfl_xor_sync(~0u, acc, 4);
            acc += __shfl_xor_sync(~0u, acc, 8);
            acc += __shfl_xor_sync(~0u, acc, 16);
            if (lane < 4) {
                int k = kbase + t * T2 + kh * 16 + it * 4 + lane;
                // faithful to source: NEG_MASK_SCALE = -1e-09
                aw[k] = acc + (-1e-9f) * (1.0f - (float)mrow[k]);
            }
        }
        __syncthreads();   // buffer `buf` is restaged next iteration
    }
}

// ---------------- Softmax + context. grid 128: (b, 8-query tile). 256 threads.
__global__ __launch_bounds__(256) void softctx_kernel(const float* __restrict__ value,
                                                      float* __restrict__ out_aw,
                                                      float* __restrict__ out_ctx) {
    __shared__ float s_w[QT3][KK];   // 32 KB

    const int tid = threadIdx.x;
    const int bx = blockIdx.x;
    const int b = bx >> 5;
    const int q0 = (bx & 31) * QT3;
    const int warp = tid >> 5;
    const int lane = tid & 31;

    // ---- softmax: warp `warp` handles row q0+warp; 32 elems per lane in regs
    {
        float* aw = out_aw + (size_t)(b * QQ + q0 + warp) * KK;
        float vals[32];
        float mx = -1e30f;
#pragma unroll
        for (int j = 0; j < 32; ++j) {
            float s = aw[lane + j * 32];
            vals[j] = s;
            mx = fmaxf(mx, s);
        }
#pragma unroll
        for (int o = 16; o; o >>= 1) mx = fmaxf(mx, __shfl_xor_sync(~0u, mx, o));
        float sum = 0.f;
#pragma unroll
        for (int j = 0; j < 32; ++j) { float e = __expf(vals[j] - mx); vals[j] = e; sum += e; }
#pragma unroll
        for (int o = 16; o; o >>= 1) sum += __shfl_xor_sync(~0u, sum, o);
        float inv = 1.0f / sum;
#pragma unroll
        for (int j = 0; j < 32; ++j) {
            float w = vals[j] * inv;
            aw[lane + j * 32] = w;
            s_w[warp][lane + j * 32] = w;
        }
    }
    __syncthreads();

    // ---- context: thread h = tid&127 handles 4 queries; value row reused
    {
        const int h = tid & 127;
        const int qg = tid >> 7;   // 0 or 1
        const float* vb = value + (size_t)b * KK * HH + h;
        const float* w0 = s_w[qg * 4 + 0];
        const float* w1 = s_w[qg * 4 + 1];
        const float* w2 = s_w[qg * 4 + 2];
        const float* w3 = s_w[qg * 4 + 3];
        float a0 = 0.f, a1 = 0.f, a2 = 0.f, a3 = 0.f;
#pragma unroll 8
        for (int k = 0; k < KK; ++k) {
            float v = vb[(size_t)k * HH];
            a0 += w0[k] * v;
            a1 += w1[k] * v;
            a2 += w2[k] * v;
            a3 += w3[k] * v;
        }
        float* ctx = out_ctx + (size_t)(b * QQ + q0 + qg * 4) * HH + h;
        ctx[0 * HH] = a0;
        ctx[1 * HH] = a1;
        ctx[2 * HH] = a2;
        ctx[3 * HH] = a3;
    }
}

extern "C" void kernel_launch(void* const* d_in, const int* in_sizes, int n_in,
                              void* d_out, int out_size) {
    // metadata order: query, key, value, mask, Wq, Wk, v
    const float* query = (const float*)d_in[0];
    const float* key   = (const float*)d_in[1];
    const float* value = (const float*)d_in[2];
    const int*   mask  = (const int*)d_in[3];
    const float* Wq    = (const float*)d_in[4];
    const float* Wk    = (const float*)d_in[5];
    const float* vvec  = (const float*)d_in[6];

    float* out_aw  = (float*)d_out;                          // (B,Q,K)
    float* out_ctx = out_aw + (size_t)BB * QQ * KK;          // (B,Q,H)

    proj_kernel<<<160, 256>>>(query, key, Wq, Wk);
    score_kernel<<<BB * (QQ / QT) * KS, 256>>>(mask, vvec, out_aw);
    softctx_kernel<<<BB * (QQ / QT3), 256>>>(value, out_aw, out_ctx);
}

// round 6
// speedup vs baseline: 1.0697x; 1.0697x over previous
#include <cuda_runtime.h>
#include <cuda_bf16.h>
#include <cstdint>

// Problem constants (B=4, Q=256, K=1024, H=128)
#define BB 4
#define QQ 256
#define KK 1024
#define HH 128
#define QT 4            // queries per score block
#define KS 8            // k-splits per query row
#define KCH (KK / KS)   // 128 k-rows per block
#define T2 32           // k-rows per stage tile
#define P4 33           // float4 pitch of kp tile row
#define QT3 8           // queries per softmax/ctx block

// Scratch for projections (device globals — no allocation allowed)
__device__ float g_qp[BB * QQ * HH];   // 512 KB
__device__ float g_kp[BB * KK * HH];   // 2 MB

__device__ __forceinline__ float fast_tanh(float x) {
    float y;
    asm("tanh.approx.f32 %0, %1;" : "=f"(y) : "f"(x));
    return y;
}

__device__ __forceinline__ void cp_async16(void* dst, const void* src) {
    uint32_t d = (uint32_t)__cvta_generic_to_shared(dst);
    asm volatile("cp.async.ca.shared.global [%0], [%1], 16;\n" :: "r"(d), "l"(src));
}

// ---------------- Fused projection GEMM: out[row][h] = sum_d in[row][d] * W[h][d]
// 32x64 tile per block, 256 threads (16x16), 2x4 register tile.
// blocks 0..63: q-proj (1024 rows), blocks 64..319: k-proj (4096 rows)
__global__ __launch_bounds__(256) void proj_kernel(
    const float* __restrict__ query, const float* __restrict__ key,
    const float* __restrict__ Wq, const float* __restrict__ Wk) {
    __shared__ float s_a[32 * 36];
    __shared__ float s_b[64 * 36];

    int bx = blockIdx.x;
    const float* in; const float* W; float* out;
    int rowTile, hTile;
    if (bx < 64) { in = query; W = Wq; out = g_qp; rowTile = (bx >> 1) * 32; hTile = (bx & 1) * 64; }
    else { bx -= 64; in = key; W = Wk; out = g_kp; rowTile = (bx >> 1) * 32; hTile = (bx & 1) * 64; }

    const int tid = threadIdx.x;
    const int tx = tid & 15;
    const int ty = tid >> 4;

    float acc[2][4] = {};

    for (int kc = 0; kc < 4; ++kc) {
        __syncthreads();
        {
            // s_a: 32 rows x 32 cols = 256 float4 (1 per thread)
            int r = tid >> 3, c = tid & 7;
            ((float4*)s_a)[r * 9 + c] =
                ((const float4*)(in + (size_t)(rowTile + r) * HH + kc * 32))[c];
            // s_b: 64 rows x 32 cols = 512 float4 (2 per thread)
            int idx = tid;
#pragma unroll
            for (int i = 0; i < 2; ++i, idx += 256) {
                int rb = idx >> 3, cb = idx & 7;
                ((float4*)s_b)[rb * 9 + cb] =
                    ((const float4*)(W + (size_t)(hTile + rb) * HH + kc * 32))[cb];
            }
        }
        __syncthreads();

#pragma unroll
        for (int s = 0; s < 8; ++s) {
            float4 a[2], b[4];
#pragma unroll
            for (int i = 0; i < 2; ++i) a[i] = ((const float4*)s_a)[(ty + 16 * i) * 9 + s];
#pragma unroll
            for (int j = 0; j < 4; ++j) b[j] = ((const float4*)s_b)[(tx + 16 * j) * 9 + s];
#pragma unroll
            for (int i = 0; i < 2; ++i)
#pragma unroll
                for (int j = 0; j < 4; ++j)
                    acc[i][j] += a[i].x * b[j].x + a[i].y * b[j].y
                               + a[i].z * b[j].z + a[i].w * b[j].w;
        }
    }

#pragma unroll
    for (int i = 0; i < 2; ++i)
#pragma unroll
        for (int j = 0; j < 4; ++j)
            out[(size_t)(rowTile + ty + 16 * i) * HH + hTile + tx + 16 * j] = acc[i][j];
}

// ---------------- Score kernel: masked raw scores -> out_aw (scratch).
// grid 2048: bx = ((b*64) + qt)*8 + ks. Block 256 thr, 8 warps: q = w&3, kh = w>>2.
// Thread: hs = lane>>2 (h-slice of 16 floats), ksub = lane&3.
__global__ __launch_bounds__(256, 3) void score_kernel(const int* __restrict__ mask,
                                                       const float* __restrict__ vvec,
                                                       float* __restrict__ out_aw) {
    __shared__ float4 s_kp[2][T2 * P4];

    const int tid = threadIdx.x;
    const int bx = blockIdx.x;
    const int b = bx >> 9;
    const int qt = (bx >> 3) & 63;
    const int ks = bx & 7;
    const int q0 = qt * QT;
    const int kbase = ks * KCH;
    const int warp = tid >> 5;
    const int lane = tid & 31;
    const int q = warp & 3;
    const int kh = warp >> 2;
    const int hs = lane >> 2;
    const int ksub = lane & 3;

    const float4* kp4 = (const float4*)g_kp + ((size_t)b * KK + kbase) * (HH / 4);

    float4 qq[4], vv[4];
    {
        const float4* qp = (const float4*)g_qp + (size_t)(b * QQ + q0 + q) * (HH / 4) + hs * 4;
        const float4* v4 = (const float4*)vvec + hs * 4;
#pragma unroll
        for (int i = 0; i < 4; ++i) { qq[i] = qp[i]; vv[i] = v4[i]; }
    }

    const int bq = b * QQ + q0 + q;
    const int* mrow = mask + (size_t)bq * KK;
    float* aw = out_aw + (size_t)bq * KK;

    auto stage = [&](int t, int buf) {
        const float4* src = kp4 + (size_t)t * T2 * (HH / 4);
        float4* dst = &s_kp[buf][0];
#pragma unroll
        for (int i = 0; i < 4; ++i) {
            int idx = tid + i * 256;              // 0..1023
            int r = idx >> 5, c = idx & 31;
            cp_async16(dst + r * P4 + c, src + idx);
        }
        asm volatile("cp.async.commit_group;\n");
    };

    stage(0, 0);
    for (int t = 0; t < KCH / T2; ++t) {
        const int buf = t & 1;
        if (t < KCH / T2 - 1) {
            stage(t + 1, buf ^ 1);
            asm volatile("cp.async.wait_group 1;\n");
        } else {
            asm volatile("cp.async.wait_group 0;\n");
        }
        __syncthreads();

        const float4* base = &s_kp[buf][0] + hs * 4;
#pragma unroll
        for (int it = 0; it < 4; ++it) {
            const int kk = kh * 16 + it * 4 + ksub;
            const float4* kr = base + kk * P4;
            float4 k0v = kr[0], k1v = kr[1], k2v = kr[2], k3v = kr[3];
            float a0 = 0.f, a1 = 0.f;
            a0 += vv[0].x * fast_tanh(qq[0].x + k0v.x);
            a0 += vv[0].y * fast_tanh(qq[0].y + k0v.y);
            a0 += vv[0].z * fast_tanh(qq[0].z + k0v.z);
            a0 += vv[0].w * fast_tanh(qq[0].w + k0v.w);
            a1 += vv[1].x * fast_tanh(qq[1].x + k1v.x);
            a1 += vv[1].y * fast_tanh(qq[1].y + k1v.y);
            a1 += vv[1].z * fast_tanh(qq[1].z + k1v.z);
            a1 += vv[1].w * fast_tanh(qq[1].w + k1v.w);
            a0 += vv[2].x * fast_tanh(qq[2].x + k2v.x);
            a0 += vv[2].y * fast_tanh(qq[2].y + k2v.y);
            a0 += vv[2].z * fast_tanh(qq[2].z + k2v.z);
            a0 += vv[2].w * fast_tanh(qq[2].w + k2v.w);
            a1 += vv[3].x * fast_tanh(qq[3].x + k3v.x);
            a1 += vv[3].y * fast_tanh(qq[3].y + k3v.y);
            a1 += vv[3].z * fast_tanh(qq[3].z + k3v.z);
            a1 += vv[3].w * fast_tanh(qq[3].w + k3v.w);
            float acc = a0 + a1;
            acc += __shfl_xor_sync(~0u, acc, 4);
            acc += __shfl_xor_sync(~0u, acc, 8);
            acc += __shfl_xor_sync(~0u, acc, 16);
            if (lane < 4) {
                int k = kbase + t * T2 + kh * 16 + it * 4 + lane;
                // faithful to source: NEG_MASK_SCALE = -1e-09
                aw[k] = acc + (-1e-9f) * (1.0f - (float)mrow[k]);
            }
        }
        __syncthreads();   // buffer `buf` is restaged next iteration
    }
}

// ---------------- Softmax + context. grid 128: (b, 8-query tile). 256 threads.
__global__ __launch_bounds__(256) void softctx_kernel(const float* __restrict__ value,
                                                      float* __restrict__ out_aw,
                                                      float* __restrict__ out_ctx) {
    __shared__ float s_w[QT3][KK];   // 32 KB

    const int tid = threadIdx.x;
    const int bx = blockIdx.x;
    const int b = bx >> 5;
    const int q0 = (bx & 31) * QT3;
    const int warp = tid >> 5;
    const int lane = tid & 31;

    // ---- softmax: warp `warp` handles row q0+warp; 32 elems per lane in regs
    {
        float* aw = out_aw + (size_t)(b * QQ + q0 + warp) * KK;
        float vals[32];
        float mx = -1e30f;
#pragma unroll
        for (int j = 0; j < 32; ++j) {
            float s = aw[lane + j * 32];
            vals[j] = s;
            mx = fmaxf(mx, s);
        }
#pragma unroll
        for (int o = 16; o; o >>= 1) mx = fmaxf(mx, __shfl_xor_sync(~0u, mx, o));
        float sum = 0.f;
#pragma unroll
        for (int j = 0; j < 32; ++j) { float e = __expf(vals[j] - mx); vals[j] = e; sum += e; }
#pragma unroll
        for (int o = 16; o; o >>= 1) sum += __shfl_xor_sync(~0u, sum, o);
        float inv = 1.0f / sum;
#pragma unroll
        for (int j = 0; j < 32; ++j) {
            float w = vals[j] * inv;
            aw[lane + j * 32] = w;
            s_w[warp][lane + j * 32] = w;
        }
    }
    __syncthreads();

    // ---- context: thread h = tid&127 handles 4 queries; value row reused
    {
        const int h = tid & 127;
        const int qg = tid >> 7;   // 0 or 1
        const float* vb = value + (size_t)b * KK * HH + h;
        const float* w0 = s_w[qg * 4 + 0];
        const float* w1 = s_w[qg * 4 + 1];
        const float* w2 = s_w[qg * 4 + 2];
        const float* w3 = s_w[qg * 4 + 3];
        float a0 = 0.f, a1 = 0.f, a2 = 0.f, a3 = 0.f;
#pragma unroll 8
        for (int k = 0; k < KK; ++k) {
            float v = vb[(size_t)k * HH];
            a0 += w0[k] * v;
            a1 += w1[k] * v;
            a2 += w2[k] * v;
            a3 += w3[k] * v;
        }
        float* ctx = out_ctx + (size_t)(b * QQ + q0 + qg * 4) * HH + h;
        ctx[0 * HH] = a0;
        ctx[1 * HH] = a1;
        ctx[2 * HH] = a2;
        ctx[3 * HH] = a3;
    }
}

extern "C" void kernel_launch(void* const* d_in, const int* in_sizes, int n_in,
                              void* d_out, int out_size) {
    // metadata order: query, key, value, mask, Wq, Wk, v
    const float* query = (const float*)d_in[0];
    const float* key   = (const float*)d_in[1];
    const float* value = (const float*)d_in[2];
    const int*   mask  = (const int*)d_in[3];
    const float* Wq    = (const float*)d_in[4];
    const float* Wk    = (const float*)d_in[5];
    const float* vvec  = (const float*)d_in[6];

    float* out_aw  = (float*)d_out;                          // (B,Q,K)
    float* out_ctx = out_aw + (size_t)BB * QQ * KK;          // (B,Q,H)

    proj_kernel<<<320, 256>>>(query, key, Wq, Wk);
    score_kernel<<<BB * (QQ / QT) * KS, 256>>>(mask, vvec, out_aw);
    softctx_kernel<<<BB * (QQ / QT3), 256>>>(value, out_aw, out_ctx);
}

// round 7
// speedup vs baseline: 1.0730x; 1.0031x over previous
#include <cuda_runtime.h>
#include <cuda_bf16.h>
#include <cuda_fp16.h>
#include <cstdint>

// Problem constants (B=4, Q=256, K=1024, H=128)
#define BB 4
#define QQ 256
#define KK 1024
#define HH 128
#define QT 4            // queries per score block
#define KS 8            // k-splits per query row
#define KCH (KK / KS)   // 128 k-rows per block
#define T2 32           // k-rows per stage tile
#define P4 33           // float4 pitch of kp tile row
#define QT3 8           // queries per softmax/ctx block

// Scratch for projections (device globals — no allocation allowed)
__device__ float g_qp[BB * QQ * HH];   // 512 KB
__device__ float g_kp[BB * KK * HH];   // 2 MB

// Two tanhs in one MUFU op (f16x2). Inputs/outputs f32; only tanh I/O is f16.
__device__ __forceinline__ float2 tanh2(float a, float b) {
    __half2 h = __float22half2_rn(make_float2(a, b));
    uint32_t hv = *reinterpret_cast<uint32_t*>(&h);
    uint32_t r;
    asm("tanh.approx.f16x2 %0, %1;" : "=r"(r) : "r"(hv));
    __half2 hr = *reinterpret_cast<__half2*>(&r);
    return __half22float2(hr);
}

__device__ __forceinline__ void cp_async16(void* dst, const void* src) {
    uint32_t d = (uint32_t)__cvta_generic_to_shared(dst);
    asm volatile("cp.async.ca.shared.global [%0], [%1], 16;\n" :: "r"(d), "l"(src));
}

// ---------------- Fused projection GEMM: out[row][h] = sum_d in[row][d] * W[h][d]
// 32x64 tile per block, 256 threads (16x16), 2x4 register tile.
// blocks 0..63: q-proj (1024 rows), blocks 64..319: k-proj (4096 rows)
__global__ __launch_bounds__(256) void proj_kernel(
    const float* __restrict__ query, const float* __restrict__ key,
    const float* __restrict__ Wq, const float* __restrict__ Wk) {
    __shared__ float s_a[32 * 36];
    __shared__ float s_b[64 * 36];

    int bx = blockIdx.x;
    const float* in; const float* W; float* out;
    int rowTile, hTile;
    if (bx < 64) { in = query; W = Wq; out = g_qp; rowTile = (bx >> 1) * 32; hTile = (bx & 1) * 64; }
    else { bx -= 64; in = key; W = Wk; out = g_kp; rowTile = (bx >> 1) * 32; hTile = (bx & 1) * 64; }

    const int tid = threadIdx.x;
    const int tx = tid & 15;
    const int ty = tid >> 4;

    float acc[2][4] = {};

    for (int kc = 0; kc < 4; ++kc) {
        __syncthreads();
        {
            int r = tid >> 3, c = tid & 7;
            ((float4*)s_a)[r * 9 + c] =
                ((const float4*)(in + (size_t)(rowTile + r) * HH + kc * 32))[c];
            int idx = tid;
#pragma unroll
            for (int i = 0; i < 2; ++i, idx += 256) {
                int rb = idx >> 3, cb = idx & 7;
                ((float4*)s_b)[rb * 9 + cb] =
                    ((const float4*)(W + (size_t)(hTile + rb) * HH + kc * 32))[cb];
            }
        }
        __syncthreads();

#pragma unroll
        for (int s = 0; s < 8; ++s) {
            float4 a[2], b[4];
#pragma unroll
            for (int i = 0; i < 2; ++i) a[i] = ((const float4*)s_a)[(ty + 16 * i) * 9 + s];
#pragma unroll
            for (int j = 0; j < 4; ++j) b[j] = ((const float4*)s_b)[(tx + 16 * j) * 9 + s];
#pragma unroll
            for (int i = 0; i < 2; ++i)
#pragma unroll
                for (int j = 0; j < 4; ++j)
                    acc[i][j] += a[i].x * b[j].x + a[i].y * b[j].y
                               + a[i].z * b[j].z + a[i].w * b[j].w;
        }
    }

#pragma unroll
    for (int i = 0; i < 2; ++i)
#pragma unroll
        for (int j = 0; j < 4; ++j)
            out[(size_t)(rowTile + ty + 16 * i) * HH + hTile + tx + 16 * j] = acc[i][j];
}

// ---------------- Score kernel: masked raw scores -> out_aw (scratch).
// grid 2048: bx = ((b*64) + qt)*8 + ks. Block 256 thr, 8 warps: q = w&3, kh = w>>2.
// Thread: hs = lane>>2 (h-slice of 16 floats), ksub = lane&3.
__global__ __launch_bounds__(256, 3) void score_kernel(const int* __restrict__ mask,
                                                       const float* __restrict__ vvec,
                                                       float* __restrict__ out_aw) {
    __shared__ float4 s_kp[2][T2 * P4];

    const int tid = threadIdx.x;
    const int bx = blockIdx.x;
    const int b = bx >> 9;
    const int qt = (bx >> 3) & 63;
    const int ks = bx & 7;
    const int q0 = qt * QT;
    const int kbase = ks * KCH;
    const int warp = tid >> 5;
    const int lane = tid & 31;
    const int q = warp & 3;
    const int kh = warp >> 2;
    const int hs = lane >> 2;
    const int ksub = lane & 3;

    const float4* kp4 = (const float4*)g_kp + ((size_t)b * KK + kbase) * (HH / 4);

    float4 qq[4], vv[4];
    {
        const float4* qp = (const float4*)g_qp + (size_t)(b * QQ + q0 + q) * (HH / 4) + hs * 4;
        const float4* v4 = (const float4*)vvec + hs * 4;
#pragma unroll
        for (int i = 0; i < 4; ++i) { qq[i] = qp[i]; vv[i] = v4[i]; }
    }

    const int bq = b * QQ + q0 + q;
    const int* mrow = mask + (size_t)bq * KK;
    float* aw = out_aw + (size_t)bq * KK;

    auto stage = [&](int t, int buf) {
        const float4* src = kp4 + (size_t)t * T2 * (HH / 4);
        float4* dst = &s_kp[buf][0];
#pragma unroll
        for (int i = 0; i < 4; ++i) {
            int idx = tid + i * 256;              // 0..1023
            int r = idx >> 5, c = idx & 31;
            cp_async16(dst + r * P4 + c, src + idx);
        }
        asm volatile("cp.async.commit_group;\n");
    };

    stage(0, 0);
    for (int t = 0; t < KCH / T2; ++t) {
        const int buf = t & 1;
        if (t < KCH / T2 - 1) {
            stage(t + 1, buf ^ 1);
            asm volatile("cp.async.wait_group 1;\n");
        } else {
            asm volatile("cp.async.wait_group 0;\n");
        }
        __syncthreads();

        const float4* base = &s_kp[buf][0] + hs * 4;
#pragma unroll
        for (int it = 0; it < 4; ++it) {
            const int kk = kh * 16 + it * 4 + ksub;
            const float4* kr = base + kk * P4;
            float4 k0v = kr[0], k1v = kr[1], k2v = kr[2], k3v = kr[3];
            float a0 = 0.f, a1 = 0.f;
            {
                float2 t01 = tanh2(qq[0].x + k0v.x, qq[0].y + k0v.y);
                float2 t23 = tanh2(qq[0].z + k0v.z, qq[0].w + k0v.w);
                a0 += vv[0].x * t01.x; a0 += vv[0].y * t01.y;
                a1 += vv[0].z * t23.x; a1 += vv[0].w * t23.y;
            }
            {
                float2 t01 = tanh2(qq[1].x + k1v.x, qq[1].y + k1v.y);
                float2 t23 = tanh2(qq[1].z + k1v.z, qq[1].w + k1v.w);
                a0 += vv[1].x * t01.x; a0 += vv[1].y * t01.y;
                a1 += vv[1].z * t23.x; a1 += vv[1].w * t23.y;
            }
            {
                float2 t01 = tanh2(qq[2].x + k2v.x, qq[2].y + k2v.y);
                float2 t23 = tanh2(qq[2].z + k2v.z, qq[2].w + k2v.w);
                a0 += vv[2].x * t01.x; a0 += vv[2].y * t01.y;
                a1 += vv[2].z * t23.x; a1 += vv[2].w * t23.y;
            }
            {
                float2 t01 = tanh2(qq[3].x + k3v.x, qq[3].y + k3v.y);
                float2 t23 = tanh2(qq[3].z + k3v.z, qq[3].w + k3v.w);
                a0 += vv[3].x * t01.x; a0 += vv[3].y * t01.y;
                a1 += vv[3].z * t23.x; a1 += vv[3].w * t23.y;
            }
            float acc = a0 + a1;
            acc += __shfl_xor_sync(~0u, acc, 4);
            acc += __shfl_xor_sync(~0u, acc, 8);
            acc += __shfl_xor_sync(~0u, acc, 16);
            if (lane < 4) {
                int k = kbase + t * T2 + kh * 16 + it * 4 + lane;
                // faithful to source: NEG_MASK_SCALE = -1e-09
                aw[k] = acc + (-1e-9f) * (1.0f - (float)mrow[k]);
            }
        }
        __syncthreads();   // buffer `buf` is restaged next iteration
    }
}

// ---------------- Softmax + context. grid 128: (b, 8-query tile). 256 threads.
__global__ __launch_bounds__(256) void softctx_kernel(const float* __restrict__ value,
                                                      float* __restrict__ out_aw,
                                                      float* __restrict__ out_ctx) {
    __shared__ float s_w[QT3][KK];   // 32 KB

    const int tid = threadIdx.x;
    const int bx = blockIdx.x;
    const int b = bx >> 5;
    const int q0 = (bx & 31) * QT3;
    const int warp = tid >> 5;
    const int lane = tid & 31;

    // ---- softmax: warp `warp` handles row q0+warp; 32 elems per lane in regs
    {
        float* aw = out_aw + (size_t)(b * QQ + q0 + warp) * KK;
        float vals[32];
        float mx = -1e30f;
#pragma unroll
        for (int j = 0; j < 32; ++j) {
            float s = aw[lane + j * 32];
            vals[j] = s;
            mx = fmaxf(mx, s);
        }
#pragma unroll
        for (int o = 16; o; o >>= 1) mx = fmaxf(mx, __shfl_xor_sync(~0u, mx, o));
        float sum = 0.f;
#pragma unroll
        for (int j = 0; j < 32; ++j) { float e = __expf(vals[j] - mx); vals[j] = e; sum += e; }
#pragma unroll
        for (int o = 16; o; o >>= 1) sum += __shfl_xor_sync(~0u, sum, o);
        float inv = 1.0f / sum;
#pragma unroll
        for (int j = 0; j < 32; ++j) {
            float w = vals[j] * inv;
            aw[lane + j * 32] = w;
            s_w[warp][lane + j * 32] = w;
        }
    }
    __syncthreads();

    // ---- context: thread h = tid&127 handles 4 queries; value row reused
    {
        const int h = tid & 127;
        const int qg = tid >> 7;   // 0 or 1
        const float* vb = value + (size_t)b * KK * HH + h;
        const float* w0 = s_w[qg * 4 + 0];
        const float* w1 = s_w[qg * 4 + 1];
        const float* w2 = s_w[qg * 4 + 2];
        const float* w3 = s_w[qg * 4 + 3];
        float a0 = 0.f, a1 = 0.f, a2 = 0.f, a3 = 0.f;
#pragma unroll 8
        for (int k = 0; k < KK; ++k) {
            float v = vb[(size_t)k * HH];
            a0 += w0[k] * v;
            a1 += w1[k] * v;
            a2 += w2[k] * v;
            a3 += w3[k] * v;
        }
        float* ctx = out_ctx + (size_t)(b * QQ + q0 + qg * 4) * HH + h;
        ctx[0 * HH] = a0;
        ctx[1 * HH] = a1;
        ctx[2 * HH] = a2;
        ctx[3 * HH] = a3;
    }
}

extern "C" void kernel_launch(void* const* d_in, const int* in_sizes, int n_in,
                              void* d_out, int out_size) {
    // metadata order: query, key, value, mask, Wq, Wk, v
    const float* query = (const float*)d_in[0];
    const float* key   = (const float*)d_in[1];
    const float* value = (const float*)d_in[2];
    const int*   mask  = (const int*)d_in[3];
    const float* Wq    = (const float*)d_in[4];
    const float* Wk    = (const float*)d_in[5];
    const float* vvec  = (const float*)d_in[6];

    float* out_aw  = (float*)d_out;                          // (B,Q,K)
    float* out_ctx = out_aw + (size_t)BB * QQ * KK;          // (B,Q,H)

    proj_kernel<<<320, 256>>>(query, key, Wq, Wk);
    score_kernel<<<BB * (QQ / QT) * KS, 256>>>(mask, vvec, out_aw);
    softctx_kernel<<<BB * (QQ / QT3), 256>>>(value, out_aw, out_ctx);
}

// round 8
// speedup vs baseline: 1.1291x; 1.0523x over previous
#include <cuda_runtime.h>
#include <cuda_bf16.h>
#include <cuda_fp16.h>
#include <cstdint>
#include <cstring>

// Problem constants (B=4, Q=256, K=1024, H=128)
#define BB 4
#define QQ 256
#define KK 1024
#define HH 128
#define QT 4             // queries per score block
#define KS 8             // k-splits per query row
#define KCH (KK / KS)    // 128 k-rows per block
#define T2 32            // k-rows per stage tile
#define PITCHB 272       // bytes per smem tile row (256 data + 16 pad)
#define TILEB (T2 * PITCHB)  // 8704 bytes per buffer
#define QT3 8            // queries per softmax/ctx block

// Scratch: projections stored in f16 (device globals — no allocation allowed)
__device__ __half g_qp[BB * QQ * HH];   // 256 KB
__device__ __half g_kp[BB * KK * HH];   // 1 MB

__device__ __forceinline__ uint32_t h2u(__half2 h) { uint32_t u; memcpy(&u, &h, 4); return u; }
__device__ __forceinline__ __half2 u2h(uint32_t u) { __half2 h; memcpy(&h, &u, 4); return h; }

__device__ __forceinline__ uint32_t htanh2(uint32_t a) {
    uint32_t r;
    asm("tanh.approx.f16x2 %0, %1;" : "=r"(r) : "r"(a));
    return r;
}

__device__ __forceinline__ void cp_async16(void* dst, const void* src) {
    uint32_t d = (uint32_t)__cvta_generic_to_shared(dst);
    asm volatile("cp.async.ca.shared.global [%0], [%1], 16;\n" :: "r"(d), "l"(src));
}

// ---------------- Fused projection GEMM: out[row][h] = sum_d in[row][d] * W[h][d]
// f32 compute, f16 store. 32x64 tile per block, 256 threads, 2x4 register tile.
__global__ __launch_bounds__(256) void proj_kernel(
    const float* __restrict__ query, const float* __restrict__ key,
    const float* __restrict__ Wq, const float* __restrict__ Wk) {
    __shared__ float s_a[32 * 36];
    __shared__ float s_b[64 * 36];

    int bx = blockIdx.x;
    const float* in; const float* W; __half* out;
    int rowTile, hTile;
    if (bx < 64) { in = query; W = Wq; out = g_qp; rowTile = (bx >> 1) * 32; hTile = (bx & 1) * 64; }
    else { bx -= 64; in = key; W = Wk; out = g_kp; rowTile = (bx >> 1) * 32; hTile = (bx & 1) * 64; }

    const int tid = threadIdx.x;
    const int tx = tid & 15;
    const int ty = tid >> 4;

    float acc[2][4] = {};

    for (int kc = 0; kc < 4; ++kc) {
        __syncthreads();
        {
            int r = tid >> 3, c = tid & 7;
            ((float4*)s_a)[r * 9 + c] =
                ((const float4*)(in + (size_t)(rowTile + r) * HH + kc * 32))[c];
            int idx = tid;
#pragma unroll
            for (int i = 0; i < 2; ++i, idx += 256) {
                int rb = idx >> 3, cb = idx & 7;
                ((float4*)s_b)[rb * 9 + cb] =
                    ((const float4*)(W + (size_t)(hTile + rb) * HH + kc * 32))[cb];
            }
        }
        __syncthreads();

#pragma unroll
        for (int s = 0; s < 8; ++s) {
            float4 a[2], b[4];
#pragma unroll
            for (int i = 0; i < 2; ++i) a[i] = ((const float4*)s_a)[(ty + 16 * i) * 9 + s];
#pragma unroll
            for (int j = 0; j < 4; ++j) b[j] = ((const float4*)s_b)[(tx + 16 * j) * 9 + s];
#pragma unroll
            for (int i = 0; i < 2; ++i)
#pragma unroll
                for (int j = 0; j < 4; ++j)
                    acc[i][j] += a[i].x * b[j].x + a[i].y * b[j].y
                               + a[i].z * b[j].z + a[i].w * b[j].w;
        }
    }

#pragma unroll
    for (int i = 0; i < 2; ++i)
#pragma unroll
        for (int j = 0; j < 4; ++j)
            out[(size_t)(rowTile + ty + 16 * i) * HH + hTile + tx + 16 * j] =
                __float2half(acc[i][j]);
}

// ---------------- Score kernel: HMMA over tanh(qp+kp) features.
// grid 2048: bx = ((b*64)+qt)*8+ks. 8 warps: q = w&3, kh = w>>2.
// Warp processes 16 k-rows per 32-row tile (rows kh*16..kh*16+15), 4 tiles.
// Per 16x16 chunk: ldmatrix.x4 -> HADD2(qp) -> tanh.f16x2 -> mma.m16n8k16 (B = v).
__global__ __launch_bounds__(256, 3) void score_kernel(const int* __restrict__ mask,
                                                       const float* __restrict__ vvec,
                                                       float* __restrict__ out_aw) {
    __shared__ __align__(16) unsigned char s_kp[2][TILEB];

    const int tid = threadIdx.x;
    const int bx = blockIdx.x;
    const int b = bx >> 9;
    const int qt = (bx >> 3) & 63;
    const int ks = bx & 7;
    const int q0 = qt * QT;
    const int kbase = ks * KCH;
    const int warp = tid >> 5;
    const int lane = tid & 31;
    const int q = warp & 3;
    const int kh = warp >> 2;
    const int t4 = lane & 3;          // thread-in-group
    const int grp = lane >> 2;        // group id (row within 8)

    // qp fragment (A-layout cols): per chunk c, half2 at h2-index 8c+t4 and 8c+t4+4
    // v fragment (B k-rows): identical h2 indices (B col-major k16n8, n-independent)
    uint32_t qf[16], vf[16];
    {
        const __half2* qrow = (const __half2*)(g_qp + (size_t)(b * QQ + q0 + q) * HH);
#pragma unroll
        for (int c = 0; c < 8; ++c) {
            qf[2 * c]     = h2u(qrow[8 * c + t4]);
            qf[2 * c + 1] = h2u(qrow[8 * c + t4 + 4]);
            vf[2 * c]     = h2u(__floats2half2_rn(vvec[16 * c + 2 * t4],
                                                  vvec[16 * c + 2 * t4 + 1]));
            vf[2 * c + 1] = h2u(__floats2half2_rn(vvec[16 * c + 2 * t4 + 8],
                                                  vvec[16 * c + 2 * t4 + 9]));
        }
    }

    const int bq = b * QQ + q0 + q;
    const int* mrow = mask + (size_t)bq * KK;
    float* aw = out_aw + (size_t)bq * KK;

    // global kp source for this block's 128 k-rows (f16: 256B per row)
    const char* kp_src = (const char*)(g_kp + ((size_t)b * KK + kbase) * HH);

    auto stage = [&](int t, int buf) {
        const char* src = kp_src + (size_t)t * T2 * 256;
        unsigned char* dst = &s_kp[buf][0];
#pragma unroll
        for (int i = 0; i < 2; ++i) {
            int c = tid + i * 256;               // 0..511 16B-chunks
            int r = c >> 4, col = c & 15;
            cp_async16(dst + r * PITCHB + col * 16, src + c * 16);
        }
        asm volatile("cp.async.commit_group;\n");
    };

    // ldmatrix lane address: quad = lane>>3: row = kh*16 + (quad&1)*8 + (lane&7),
    // byte offset 16 for quads 2,3 (cols 8-15).
    uint32_t sbase = (uint32_t)__cvta_generic_to_shared(&s_kp[0][0]);
    const int lrow = kh * 16 + ((lane >> 3) & 1) * 8 + (lane & 7);
    const uint32_t laddr0 = sbase + (uint32_t)lrow * PITCHB + ((lane >> 4) ? 16u : 0u);

    stage(0, 0);
    for (int tt = 0; tt < KCH / T2; ++tt) {
        const int buf = tt & 1;
        if (tt < KCH / T2 - 1) {
            stage(tt + 1, buf ^ 1);
            asm volatile("cp.async.wait_group 1;\n");
        } else {
            asm volatile("cp.async.wait_group 0;\n");
        }
        __syncthreads();

        const uint32_t maddr = laddr0 + (uint32_t)buf * TILEB;
        float f0 = 0.f, f1 = 0.f, f2 = 0.f, f3 = 0.f;
#pragma unroll
        for (int c = 0; c < 8; ++c) {
            uint32_t a0, a1, a2, a3;
            asm volatile("ldmatrix.sync.aligned.m8n8.x4.shared.b16 {%0,%1,%2,%3}, [%4];"
                         : "=r"(a0), "=r"(a1), "=r"(a2), "=r"(a3)
                         : "r"(maddr + 32u * c));
            a0 = htanh2(h2u(__hadd2(u2h(a0), u2h(qf[2 * c]))));
            a1 = htanh2(h2u(__hadd2(u2h(a1), u2h(qf[2 * c]))));
            a2 = htanh2(h2u(__hadd2(u2h(a2), u2h(qf[2 * c + 1]))));
            a3 = htanh2(h2u(__hadd2(u2h(a3), u2h(qf[2 * c + 1]))));
            asm volatile("mma.sync.aligned.m16n8k16.row.col.f32.f16.f16.f32 "
                         "{%0,%1,%2,%3}, {%4,%5,%6,%7}, {%8,%9}, {%0,%1,%2,%3};"
                         : "+f"(f0), "+f"(f1), "+f"(f2), "+f"(f3)
                         : "r"(a0), "r"(a1), "r"(a2), "r"(a3),
                           "r"(vf[2 * c]), "r"(vf[2 * c + 1]));
        }
        // D[grp][0] = f0 (rows 0-7), D[grp+8][0] = f2 — lanes with t4==0 write scores.
        if (t4 == 0) {
            int k0 = kbase + tt * T2 + kh * 16 + grp;
            int k1 = k0 + 8;
            // faithful to source: NEG_MASK_SCALE = -1e-09
            aw[k0] = f0 + (-1e-9f) * (1.0f - (float)mrow[k0]);
            aw[k1] = f2 + (-1e-9f) * (1.0f - (float)mrow[k1]);
        }
        __syncthreads();   // buffer `buf` is restaged next iteration
    }
}

// ---------------- Softmax + context. grid 128: (b, 8-query tile). 256 threads.
__global__ __launch_bounds__(256) void softctx_kernel(const float* __restrict__ value,
                                                      float* __restrict__ out_aw,
                                                      float* __restrict__ out_ctx) {
    __shared__ float s_w[QT3][KK];   // 32 KB

    const int tid = threadIdx.x;
    const int bx = blockIdx.x;
    const int b = bx >> 5;
    const int q0 = (bx & 31) * QT3;
    const int warp = tid >> 5;
    const int lane = tid & 31;

    // ---- softmax: warp `warp` handles row q0+warp; 32 elems per lane in regs
    {
        float* aw = out_aw + (size_t)(b * QQ + q0 + warp) * KK;
        float vals[32];
        float mx = -1e30f;
#pragma unroll
        for (int j = 0; j < 32; ++j) {
            float s = aw[lane + j * 32];
            vals[j] = s;
            mx = fmaxf(mx, s);
        }
#pragma unroll
        for (int o = 16; o; o >>= 1) mx = fmaxf(mx, __shfl_xor_sync(~0u, mx, o));
        float sum = 0.f;
#pragma unroll
        for (int j = 0; j < 32; ++j) { float e = __expf(vals[j] - mx); vals[j] = e; sum += e; }
#pragma unroll
        for (int o = 16; o; o >>= 1) sum += __shfl_xor_sync(~0u, sum, o);
        float inv = 1.0f / sum;
#pragma unroll
        for (int j = 0; j < 32; ++j) {
            float w = vals[j] * inv;
            aw[lane + j * 32] = w;
            s_w[warp][lane + j * 32] = w;
        }
    }
    __syncthreads();

    // ---- context: thread h = tid&127 handles 4 queries; value row reused
    {
        const int h = tid & 127;
        const int qg = tid >> 7;   // 0 or 1
        const float* vb = value + (size_t)b * KK * HH + h;
        const float* w0 = s_w[qg * 4 + 0];
        const float* w1 = s_w[qg * 4 + 1];
        const float* w2 = s_w[qg * 4 + 2];
        const float* w3 = s_w[qg * 4 + 3];
        float a0 = 0.f, a1 = 0.f, a2 = 0.f, a3 = 0.f;
#pragma unroll 8
        for (int k = 0; k < KK; ++k) {
            float v = vb[(size_t)k * HH];
            a0 += w0[k] * v;
            a1 += w1[k] * v;
            a2 += w2[k] * v;
            a3 += w3[k] * v;
        }
        float* ctx = out_ctx + (size_t)(b * QQ + q0 + qg * 4) * HH + h;
        ctx[0 * HH] = a0;
        ctx[1 * HH] = a1;
        ctx[2 * HH] = a2;
        ctx[3 * HH] = a3;
    }
}

extern "C" void kernel_launch(void* const* d_in, const int* in_sizes, int n_in,
                              void* d_out, int out_size) {
    // metadata order: query, key, value, mask, Wq, Wk, v
    const float* query = (const float*)d_in[0];
    const float* key   = (const float*)d_in[1];
    const float* value = (const float*)d_in[2];
    const int*   mask  = (const int*)d_in[3];
    const float* Wq    = (const float*)d_in[4];
    const float* Wk    = (const float*)d_in[5];
    const float* vvec  = (const float*)d_in[6];

    float* out_aw  = (float*)d_out;                          // (B,Q,K)
    float* out_ctx = out_aw + (size_t)BB * QQ * KK;          // (B,Q,H)

    proj_kernel<<<320, 256>>>(query, key, Wq, Wk);
    score_kernel<<<BB * (QQ / QT) * KS, 256>>>(mask, vvec, out_aw);
    softctx_kernel<<<BB * (QQ / QT3), 256>>>(value, out_aw, out_ctx);
}

// round 9
// speedup vs baseline: 1.2096x; 1.0713x over previous
#include <cuda_runtime.h>
#include <cuda_bf16.h>
#include <cuda_fp16.h>
#include <cstdint>
#include <cstring>

// Problem constants (B=4, Q=256, K=1024, H=128)
#define BB 4
#define QQ 256
#define KK 1024
#define HH 128
#define QT 4             // queries per score block
#define KS 8             // k-splits per query row
#define KCH (KK / KS)    // 128 k-rows per block
#define T2 32            // k-rows per stage tile
#define PITCHB 272       // bytes per smem tile row (256 data + 16 pad)
#define TILEB (T2 * PITCHB)  // 8704 bytes per buffer
#define CKS 4            // ctx k-splits
#define CKCH (KK / CKS)  // 256
#define CQT 16           // ctx queries per block

// Scratch (device globals — no allocation allowed)
__device__ __half g_qp[BB * QQ * HH];          // 256 KB
__device__ __half g_kp[BB * KK * HH];          // 1 MB
__device__ float  g_cpart[CKS * BB * QQ * HH]; // 2 MB ctx partials

__device__ __forceinline__ uint32_t h2u(__half2 h) { uint32_t u; memcpy(&u, &h, 4); return u; }
__device__ __forceinline__ __half2 u2h(uint32_t u) { __half2 h; memcpy(&h, &u, 4); return h; }

__device__ __forceinline__ uint32_t htanh2(uint32_t a) {
    uint32_t r;
    asm("tanh.approx.f16x2 %0, %1;" : "=r"(r) : "r"(a));
    return r;
}

__device__ __forceinline__ void cp_async16(void* dst, const void* src) {
    uint32_t d = (uint32_t)__cvta_generic_to_shared(dst);
    asm volatile("cp.async.ca.shared.global [%0], [%1], 16;\n" :: "r"(d), "l"(src));
}

// ---------------- Projection GEMM: out[row][h] = sum_d in[row][d] * W[h][d]
// Whole-operand smem staging (single barrier), 32x64 tile, 2x4 register tile.
// Dynamic smem: s_a 32x128 floats (broadcast reads), s_b 64 rows x 132-pitch.
__global__ __launch_bounds__(256, 2) void proj_kernel(
    const float* __restrict__ query, const float* __restrict__ key,
    const float* __restrict__ Wq, const float* __restrict__ Wk) {
    extern __shared__ float psm[];
    float4* s_a = (float4*)psm;                   // [32][32] float4, pitch 32
    float4* s_b = (float4*)(psm + 32 * 128);      // [64][33] float4, pitch 33

    int bx = blockIdx.x;
    const float* in; const float* W; __half* out;
    int rowTile, hTile;
    if (bx < 64) { in = query; W = Wq; out = g_qp; rowTile = (bx >> 1) * 32; hTile = (bx & 1) * 64; }
    else { bx -= 64; in = key; W = Wk; out = g_kp; rowTile = (bx >> 1) * 32; hTile = (bx & 1) * 64; }

    const int tid = threadIdx.x;
    const int tx = tid & 15;
    const int ty = tid >> 4;

    // stage A: 1024 float4 (4/thread), W: 2048 float4 (8/thread)
    {
        const float4* in4 = (const float4*)(in + (size_t)rowTile * HH);
        const float4* w4 = (const float4*)(W + (size_t)hTile * HH);
        int idx = tid;
#pragma unroll
        for (int i = 0; i < 4; ++i, idx += 256) {
            int r = idx >> 5, c = idx & 31;
            s_a[r * 32 + c] = in4[r * 32 + c];
        }
        idx = tid;
#pragma unroll
        for (int i = 0; i < 8; ++i, idx += 256) {
            int r = idx >> 5, c = idx & 31;
            s_b[r * 33 + c] = w4[r * 32 + c];
        }
    }
    __syncthreads();

    float acc[2][4] = {};
#pragma unroll
    for (int s = 0; s < 32; ++s) {
        float4 a[2], b[4];
#pragma unroll
        for (int i = 0; i < 2; ++i) a[i] = s_a[(ty + 16 * i) * 32 + s];
#pragma unroll
        for (int j = 0; j < 4; ++j) b[j] = s_b[(tx + 16 * j) * 33 + s];
#pragma unroll
        for (int i = 0; i < 2; ++i)
#pragma unroll
            for (int j = 0; j < 4; ++j)
                acc[i][j] += a[i].x * b[j].x + a[i].y * b[j].y
                           + a[i].z * b[j].z + a[i].w * b[j].w;
    }

#pragma unroll
    for (int i = 0; i < 2; ++i)
#pragma unroll
        for (int j = 0; j < 4; ++j)
            out[(size_t)(rowTile + ty + 16 * i) * HH + hTile + tx + 16 * j] =
                __float2half(acc[i][j]);
}

// ---------------- Score kernel: HMMA over tanh(qp+kp) features. (unchanged from R8)
__global__ __launch_bounds__(256, 3) void score_kernel(const int* __restrict__ mask,
                                                       const float* __restrict__ vvec,
                                                       float* __restrict__ out_aw) {
    __shared__ __align__(16) unsigned char s_kp[2][TILEB];

    const int tid = threadIdx.x;
    const int bx = blockIdx.x;
    const int b = bx >> 9;
    const int qt = (bx >> 3) & 63;
    const int ks = bx & 7;
    const int q0 = qt * QT;
    const int kbase = ks * KCH;
    const int warp = tid >> 5;
    const int lane = tid & 31;
    const int q = warp & 3;
    const int kh = warp >> 2;
    const int t4 = lane & 3;
    const int grp = lane >> 2;

    uint32_t qf[16], vf[16];
    {
        const __half2* qrow = (const __half2*)(g_qp + (size_t)(b * QQ + q0 + q) * HH);
#pragma unroll
        for (int c = 0; c < 8; ++c) {
            qf[2 * c]     = h2u(qrow[8 * c + t4]);
            qf[2 * c + 1] = h2u(qrow[8 * c + t4 + 4]);
            vf[2 * c]     = h2u(__floats2half2_rn(vvec[16 * c + 2 * t4],
                                                  vvec[16 * c + 2 * t4 + 1]));
            vf[2 * c + 1] = h2u(__floats2half2_rn(vvec[16 * c + 2 * t4 + 8],
                                                  vvec[16 * c + 2 * t4 + 9]));
        }
    }

    const int bq = b * QQ + q0 + q;
    const int* mrow = mask + (size_t)bq * KK;
    float* aw = out_aw + (size_t)bq * KK;

    const char* kp_src = (const char*)(g_kp + ((size_t)b * KK + kbase) * HH);

    auto stage = [&](int t, int buf) {
        const char* src = kp_src + (size_t)t * T2 * 256;
        unsigned char* dst = &s_kp[buf][0];
#pragma unroll
        for (int i = 0; i < 2; ++i) {
            int c = tid + i * 256;
            int r = c >> 4, col = c & 15;
            cp_async16(dst + r * PITCHB + col * 16, src + c * 16);
        }
        asm volatile("cp.async.commit_group;\n");
    };

    uint32_t sbase = (uint32_t)__cvta_generic_to_shared(&s_kp[0][0]);
    const int lrow = kh * 16 + ((lane >> 3) & 1) * 8 + (lane & 7);
    const uint32_t laddr0 = sbase + (uint32_t)lrow * PITCHB + ((lane >> 4) ? 16u : 0u);

    stage(0, 0);
    for (int tt = 0; tt < KCH / T2; ++tt) {
        const int buf = tt & 1;
        if (tt < KCH / T2 - 1) {
            stage(tt + 1, buf ^ 1);
            asm volatile("cp.async.wait_group 1;\n");
        } else {
            asm volatile("cp.async.wait_group 0;\n");
        }
        __syncthreads();

        const uint32_t maddr = laddr0 + (uint32_t)buf * TILEB;
        float f0 = 0.f, f1 = 0.f, f2 = 0.f, f3 = 0.f;
#pragma unroll
        for (int c = 0; c < 8; ++c) {
            uint32_t a0, a1, a2, a3;
            asm volatile("ldmatrix.sync.aligned.m8n8.x4.shared.b16 {%0,%1,%2,%3}, [%4];"
                         : "=r"(a0), "=r"(a1), "=r"(a2), "=r"(a3)
                         : "r"(maddr + 32u * c));
            a0 = htanh2(h2u(__hadd2(u2h(a0), u2h(qf[2 * c]))));
            a1 = htanh2(h2u(__hadd2(u2h(a1), u2h(qf[2 * c]))));
            a2 = htanh2(h2u(__hadd2(u2h(a2), u2h(qf[2 * c + 1]))));
            a3 = htanh2(h2u(__hadd2(u2h(a3), u2h(qf[2 * c + 1]))));
            asm volatile("mma.sync.aligned.m16n8k16.row.col.f32.f16.f16.f32 "
                         "{%0,%1,%2,%3}, {%4,%5,%6,%7}, {%8,%9}, {%0,%1,%2,%3};"
                         : "+f"(f0), "+f"(f1), "+f"(f2), "+f"(f3)
                         : "r"(a0), "r"(a1), "r"(a2), "r"(a3),
                           "r"(vf[2 * c]), "r"(vf[2 * c + 1]));
        }
        if (t4 == 0) {
            int k0 = kbase + tt * T2 + kh * 16 + grp;
            int k1 = k0 + 8;
            // faithful to source: NEG_MASK_SCALE = -1e-09
            aw[k0] = f0 + (-1e-9f) * (1.0f - (float)mrow[k0]);
            aw[k1] = f2 + (-1e-9f) * (1.0f - (float)mrow[k1]);
        }
        __syncthreads();
    }
}

// ---------------- Softmax in-place on out_aw. Warp per row; grid 256 x 128 thr.
__global__ __launch_bounds__(128) void softmax_kernel(float* __restrict__ out_aw) {
    const int warp = threadIdx.x >> 5;
    const int lane = threadIdx.x & 31;
    const int bq = blockIdx.x * 4 + warp;

    float* aw = out_aw + (size_t)bq * KK;
    float vals[32];
    float mx = -1e30f;
#pragma unroll
    for (int j = 0; j < 32; ++j) {
        float s = aw[lane + j * 32];
        vals[j] = s;
        mx = fmaxf(mx, s);
    }
#pragma unroll
    for (int o = 16; o; o >>= 1) mx = fmaxf(mx, __shfl_xor_sync(~0u, mx, o));
    float sum = 0.f;
#pragma unroll
    for (int j = 0; j < 32; ++j) { float e = __expf(vals[j] - mx); vals[j] = e; sum += e; }
#pragma unroll
    for (int o = 16; o; o >>= 1) sum += __shfl_xor_sync(~0u, sum, o);
    float inv = 1.0f / sum;
#pragma unroll
    for (int j = 0; j < 32; ++j) aw[lane + j * 32] = vals[j] * inv;
}

// ---------------- Context partial GEMM: 16q x 128h x 256k per block.
// grid 256: bx = ((b*16+qt)*4+ks). Thread h = tid&127, qg = tid>>7 (8 queries each).
__global__ __launch_bounds__(256) void ctx_kernel(const float* __restrict__ value,
                                                  const float* __restrict__ out_aw) {
    __shared__ float s_w[CQT * CKCH];   // 16 KB

    const int tid = threadIdx.x;
    const int bx = blockIdx.x;
    const int b = bx >> 6;
    const int qt = (bx >> 2) & 15;
    const int ks = bx & 3;
    const int q0 = qt * CQT;
    const int kbase = ks * CKCH;

    // stage weights: 16 rows x 64 float4 = 1024 float4, 4/thread
    {
        int idx = tid;
#pragma unroll
        for (int i = 0; i < 4; ++i, idx += 256) {
            int r = idx >> 6, c = idx & 63;
            ((float4*)s_w)[r * 64 + c] =
                ((const float4*)(out_aw + (size_t)(b * QQ + q0 + r) * KK + kbase))[c];
        }
    }
    __syncthreads();

    const int h = tid & 127;
    const int qg = tid >> 7;     // 0 or 1 -> queries qg*8 .. qg*8+7
    const float* vb = value + ((size_t)b * KK + kbase) * HH + h;
    const float4* w4 = (const float4*)s_w + qg * 8 * 64;

    float acc[8] = {};
#pragma unroll 4
    for (int kg = 0; kg < CKCH / 4; ++kg) {
        float v0 = vb[(4 * kg + 0) * HH];
        float v1 = vb[(4 * kg + 1) * HH];
        float v2 = vb[(4 * kg + 2) * HH];
        float v3 = vb[(4 * kg + 3) * HH];
#pragma unroll
        for (int j = 0; j < 8; ++j) {
            float4 w = w4[j * 64 + kg];
            acc[j] += w.x * v0 + w.y * v1 + w.z * v2 + w.w * v3;
        }
    }

    float* dst = g_cpart + (size_t)ks * (BB * QQ * HH) + (size_t)(b * QQ + q0 + qg * 8) * HH + h;
#pragma unroll
    for (int j = 0; j < 8; ++j) dst[j * HH] = acc[j];
}

// ---------------- Reduce ctx partials. grid 512 x 256.
__global__ __launch_bounds__(256) void ctx_reduce_kernel(float* __restrict__ out_ctx) {
    int i = blockIdx.x * 256 + threadIdx.x;   // 0 .. 131071
    const int N = BB * QQ * HH;
    out_ctx[i] = (g_cpart[i] + g_cpart[N + i]) + (g_cpart[2 * N + i] + g_cpart[3 * N + i]);
}

extern "C" void kernel_launch(void* const* d_in, const int* in_sizes, int n_in,
                              void* d_out, int out_size) {
    // metadata order: query, key, value, mask, Wq, Wk, v
    const float* query = (const float*)d_in[0];
    const float* key   = (const float*)d_in[1];
    const float* value = (const float*)d_in[2];
    const int*   mask  = (const int*)d_in[3];
    const float* Wq    = (const float*)d_in[4];
    const float* Wk    = (const float*)d_in[5];
    const float* vvec  = (const float*)d_in[6];

    float* out_aw  = (float*)d_out;                          // (B,Q,K)
    float* out_ctx = out_aw + (size_t)BB * QQ * KK;          // (B,Q,H)

    const int proj_smem = (32 * 128 + 64 * 132) * (int)sizeof(float);  // 50688 B
    cudaFuncSetAttribute(proj_kernel, cudaFuncAttributeMaxDynamicSharedMemorySize, proj_smem);

    proj_kernel<<<320, 256, proj_smem>>>(query, key, Wq, Wk);
    score_kernel<<<BB * (QQ / QT) * KS, 256>>>(mask, vvec, out_aw);
    softmax_kernel<<<BB * QQ / 4, 128>>>(out_aw);
    ctx_kernel<<<BB * (QQ / CQT) * CKS, 256>>>(value, out_aw);
    ctx_reduce_kernel<<<BB * QQ * HH / 256, 256>>>(out_ctx);
}

// round 10
// speedup vs baseline: 1.3346x; 1.1033x over previous
#include <cuda_runtime.h>
#include <cuda_bf16.h>
#include <cuda_fp16.h>
#include <cstdint>
#include <cstring>

// Problem constants (B=4, Q=256, K=1024, H=128)
#define BB 4
#define QQ 256
#define KK 1024
#define HH 128
#define QT 4             // queries per score block
#define KS 8             // k-splits per query row
#define KCH (KK / KS)    // 128 k-rows per block
#define T2 32            // k-rows per stage tile
#define PITCHB 272       // bytes per smem tile row (256 data + 16 pad)
#define TILEB (T2 * PITCHB)  // 8704 bytes per buffer
#define CKS 8            // ctx k-splits
#define CKCH (KK / CKS)  // 128
#define CQT 16           // ctx queries per block

// Scratch (device globals — no allocation allowed)
__device__ __half g_qp[BB * QQ * HH];          // 256 KB
__device__ __half g_kp[BB * KK * HH];          // 1 MB
__device__ float  g_cpart[CKS * BB * QQ * HH]; // 4 MB ctx partials

__device__ __forceinline__ uint32_t h2u(__half2 h) { uint32_t u; memcpy(&u, &h, 4); return u; }
__device__ __forceinline__ __half2 u2h(uint32_t u) { __half2 h; memcpy(&h, &u, 4); return h; }

__device__ __forceinline__ uint32_t htanh2(uint32_t a) {
    uint32_t r;
    asm("tanh.approx.f16x2 %0, %1;" : "=r"(r) : "r"(a));
    return r;
}

__device__ __forceinline__ void cp_async16(void* dst, const void* src) {
    uint32_t d = (uint32_t)__cvta_generic_to_shared(dst);
    asm volatile("cp.async.ca.shared.global [%0], [%1], 16;\n" :: "r"(d), "l"(src));
}

// ---------------- Projection GEMM: out[row][h] = sum_d in[row][d] * W[h][d]
// Whole-operand smem staging (single barrier), 32x64 tile, 2x4 register tile.
__global__ __launch_bounds__(256, 2) void proj_kernel(
    const float* __restrict__ query, const float* __restrict__ key,
    const float* __restrict__ Wq, const float* __restrict__ Wk) {
    extern __shared__ float psm[];
    float4* s_a = (float4*)psm;                   // [32][32] float4, pitch 32
    float4* s_b = (float4*)(psm + 32 * 128);      // [64][33] float4, pitch 33

    int bx = blockIdx.x;
    const float* in; const float* W; __half* out;
    int rowTile, hTile;
    if (bx < 64) { in = query; W = Wq; out = g_qp; rowTile = (bx >> 1) * 32; hTile = (bx & 1) * 64; }
    else { bx -= 64; in = key; W = Wk; out = g_kp; rowTile = (bx >> 1) * 32; hTile = (bx & 1) * 64; }

    const int tid = threadIdx.x;
    const int tx = tid & 15;
    const int ty = tid >> 4;

    {
        const float4* in4 = (const float4*)(in + (size_t)rowTile * HH);
        const float4* w4 = (const float4*)(W + (size_t)hTile * HH);
        int idx = tid;
#pragma unroll
        for (int i = 0; i < 4; ++i, idx += 256) {
            int r = idx >> 5, c = idx & 31;
            s_a[r * 32 + c] = in4[r * 32 + c];
        }
        idx = tid;
#pragma unroll
        for (int i = 0; i < 8; ++i, idx += 256) {
            int r = idx >> 5, c = idx & 31;
            s_b[r * 33 + c] = w4[r * 32 + c];
        }
    }
    __syncthreads();

    float acc[2][4] = {};
#pragma unroll
    for (int s = 0; s < 32; ++s) {
        float4 a[2], b[4];
#pragma unroll
        for (int i = 0; i < 2; ++i) a[i] = s_a[(ty + 16 * i) * 32 + s];
#pragma unroll
        for (int j = 0; j < 4; ++j) b[j] = s_b[(tx + 16 * j) * 33 + s];
#pragma unroll
        for (int i = 0; i < 2; ++i)
#pragma unroll
            for (int j = 0; j < 4; ++j)
                acc[i][j] += a[i].x * b[j].x + a[i].y * b[j].y
                           + a[i].z * b[j].z + a[i].w * b[j].w;
    }

#pragma unroll
    for (int i = 0; i < 2; ++i)
#pragma unroll
        for (int j = 0; j < 4; ++j)
            out[(size_t)(rowTile + ty + 16 * i) * HH + hTile + tx + 16 * j] =
                __float2half(acc[i][j]);
}

// ---------------- Score kernel: HMMA over tanh(qp+kp) features. (unchanged)
__global__ __launch_bounds__(256, 3) void score_kernel(const int* __restrict__ mask,
                                                       const float* __restrict__ vvec,
                                                       float* __restrict__ out_aw) {
    __shared__ __align__(16) unsigned char s_kp[2][TILEB];

    const int tid = threadIdx.x;
    const int bx = blockIdx.x;
    const int b = bx >> 9;
    const int qt = (bx >> 3) & 63;
    const int ks = bx & 7;
    const int q0 = qt * QT;
    const int kbase = ks * KCH;
    const int warp = tid >> 5;
    const int lane = tid & 31;
    const int q = warp & 3;
    const int kh = warp >> 2;
    const int t4 = lane & 3;
    const int grp = lane >> 2;

    uint32_t qf[16], vf[16];
    {
        const __half2* qrow = (const __half2*)(g_qp + (size_t)(b * QQ + q0 + q) * HH);
#pragma unroll
        for (int c = 0; c < 8; ++c) {
            qf[2 * c]     = h2u(qrow[8 * c + t4]);
            qf[2 * c + 1] = h2u(qrow[8 * c + t4 + 4]);
            vf[2 * c]     = h2u(__floats2half2_rn(vvec[16 * c + 2 * t4],
                                                  vvec[16 * c + 2 * t4 + 1]));
            vf[2 * c + 1] = h2u(__floats2half2_rn(vvec[16 * c + 2 * t4 + 8],
                                                  vvec[16 * c + 2 * t4 + 9]));
        }
    }

    const int bq = b * QQ + q0 + q;
    const int* mrow = mask + (size_t)bq * KK;
    float* aw = out_aw + (size_t)bq * KK;

    const char* kp_src = (const char*)(g_kp + ((size_t)b * KK + kbase) * HH);

    auto stage = [&](int t, int buf) {
        const char* src = kp_src + (size_t)t * T2 * 256;
        unsigned char* dst = &s_kp[buf][0];
#pragma unroll
        for (int i = 0; i < 2; ++i) {
            int c = tid + i * 256;
            int r = c >> 4, col = c & 15;
            cp_async16(dst + r * PITCHB + col * 16, src + c * 16);
        }
        asm volatile("cp.async.commit_group;\n");
    };

    uint32_t sbase = (uint32_t)__cvta_generic_to_shared(&s_kp[0][0]);
    const int lrow = kh * 16 + ((lane >> 3) & 1) * 8 + (lane & 7);
    const uint32_t laddr0 = sbase + (uint32_t)lrow * PITCHB + ((lane >> 4) ? 16u : 0u);

    stage(0, 0);
    for (int tt = 0; tt < KCH / T2; ++tt) {
        const int buf = tt & 1;
        if (tt < KCH / T2 - 1) {
            stage(tt + 1, buf ^ 1);
            asm volatile("cp.async.wait_group 1;\n");
        } else {
            asm volatile("cp.async.wait_group 0;\n");
        }
        __syncthreads();

        const uint32_t maddr = laddr0 + (uint32_t)buf * TILEB;
        float f0 = 0.f, f1 = 0.f, f2 = 0.f, f3 = 0.f;
#pragma unroll
        for (int c = 0; c < 8; ++c) {
            uint32_t a0, a1, a2, a3;
            asm volatile("ldmatrix.sync.aligned.m8n8.x4.shared.b16 {%0,%1,%2,%3}, [%4];"
                         : "=r"(a0), "=r"(a1), "=r"(a2), "=r"(a3)
                         : "r"(maddr + 32u * c));
            a0 = htanh2(h2u(__hadd2(u2h(a0), u2h(qf[2 * c]))));
            a1 = htanh2(h2u(__hadd2(u2h(a1), u2h(qf[2 * c]))));
            a2 = htanh2(h2u(__hadd2(u2h(a2), u2h(qf[2 * c + 1]))));
            a3 = htanh2(h2u(__hadd2(u2h(a3), u2h(qf[2 * c + 1]))));
            asm volatile("mma.sync.aligned.m16n8k16.row.col.f32.f16.f16.f32 "
                         "{%0,%1,%2,%3}, {%4,%5,%6,%7}, {%8,%9}, {%0,%1,%2,%3};"
                         : "+f"(f0), "+f"(f1), "+f"(f2), "+f"(f3)
                         : "r"(a0), "r"(a1), "r"(a2), "r"(a3),
                           "r"(vf[2 * c]), "r"(vf[2 * c + 1]));
        }
        if (t4 == 0) {
            int k0 = kbase + tt * T2 + kh * 16 + grp;
            int k1 = k0 + 8;
            // faithful to source: NEG_MASK_SCALE = -1e-09
            aw[k0] = f0 + (-1e-9f) * (1.0f - (float)mrow[k0]);
            aw[k1] = f2 + (-1e-9f) * (1.0f - (float)mrow[k1]);
        }
        __syncthreads();
    }
}

// ---------------- Softmax in-place on out_aw. Warp per row; grid 256 x 128 thr.
__global__ __launch_bounds__(128) void softmax_kernel(float* __restrict__ out_aw) {
    const int warp = threadIdx.x >> 5;
    const int lane = threadIdx.x & 31;
    const int bq = blockIdx.x * 4 + warp;

    float* aw = out_aw + (size_t)bq * KK;
    float vals[32];
    float mx = -1e30f;
#pragma unroll
    for (int j = 0; j < 32; ++j) {
        float s = aw[lane + j * 32];
        vals[j] = s;
        mx = fmaxf(mx, s);
    }
#pragma unroll
    for (int o = 16; o; o >>= 1) mx = fmaxf(mx, __shfl_xor_sync(~0u, mx, o));
    float sum = 0.f;
#pragma unroll
    for (int j = 0; j < 32; ++j) { float e = __expf(vals[j] - mx); vals[j] = e; sum += e; }
#pragma unroll
    for (int o = 16; o; o >>= 1) sum += __shfl_xor_sync(~0u, sum, o);
    float inv = 1.0f / sum;
#pragma unroll
    for (int j = 0; j < 32; ++j) aw[lane + j * 32] = vals[j] * inv;
}

// ---------------- Context partial GEMM: 16q x 128h x 128k per block.
// grid 512: bx = ((b*16+qt)*8+ks). Thread: h4 = tid&31 (float4 h-slice),
// qg = tid>>5 (2 queries). Warp LDG.128 covers a full contiguous value row.
__global__ __launch_bounds__(256) void ctx_kernel(const float* __restrict__ value,
                                                  const float* __restrict__ out_aw) {
    __shared__ float s_w[CQT * CKCH];   // 8 KB

    const int tid = threadIdx.x;
    const int bx = blockIdx.x;
    const int b = bx >> 7;
    const int qt = (bx >> 3) & 15;
    const int ks = bx & 7;
    const int q0 = qt * CQT;
    const int kbase = ks * CKCH;

    // stage weights: 16 rows x 32 float4 = 512 float4, 2/thread
    {
        int idx = tid;
#pragma unroll
        for (int i = 0; i < 2; ++i, idx += 256) {
            int r = idx >> 5, c = idx & 31;
            ((float4*)s_w)[idx] =
                ((const float4*)(out_aw + (size_t)(b * QQ + q0 + r) * KK + kbase))[c];
        }
    }
    __syncthreads();

    const int h4 = tid & 31;
    const int qg = tid >> 5;    // queries qg*2, qg*2+1
    const float4* vb = (const float4*)(value + ((size_t)b * KK + kbase) * HH) + h4;
    const float* w0 = s_w + (qg * 2 + 0) * CKCH;
    const float* w1 = s_w + (qg * 2 + 1) * CKCH;

    float4 A0 = {0.f, 0.f, 0.f, 0.f}, A1 = {0.f, 0.f, 0.f, 0.f};
#pragma unroll 4
    for (int k = 0; k < CKCH; ++k) {
        float4 v = vb[k * 32];
        float a = w0[k], c = w1[k];
        A0.x += a * v.x; A0.y += a * v.y; A0.z += a * v.z; A0.w += a * v.w;
        A1.x += c * v.x; A1.y += c * v.y; A1.z += c * v.z; A1.w += c * v.w;
    }

    float* dst = g_cpart + (size_t)ks * (BB * QQ * HH)
               + (size_t)(b * QQ + q0 + qg * 2) * HH;
    ((float4*)dst)[h4] = A0;
    ((float4*)(dst + HH))[h4] = A1;
}

// ---------------- Reduce ctx partials (8-way). grid 512 x 256.
__global__ __launch_bounds__(256) void ctx_reduce_kernel(float* __restrict__ out_ctx) {
    int i = blockIdx.x * 256 + threadIdx.x;   // 0 .. 131071
    const int N = BB * QQ * HH;
    float s0 = g_cpart[i]         + g_cpart[N + i];
    float s1 = g_cpart[2 * N + i] + g_cpart[3 * N + i];
    float s2 = g_cpart[4 * N + i] + g_cpart[5 * N + i];
    float s3 = g_cpart[6 * N + i] + g_cpart[7 * N + i];
    out_ctx[i] = (s0 + s1) + (s2 + s3);
}

extern "C" void kernel_launch(void* const* d_in, const int* in_sizes, int n_in,
                              void* d_out, int out_size) {
    // metadata order: query, key, value, mask, Wq, Wk, v
    const float* query = (const float*)d_in[0];
    const float* key   = (const float*)d_in[1];
    const float* value = (const float*)d_in[2];
    const int*   mask  = (const int*)d_in[3];
    const float* Wq    = (const float*)d_in[4];
    const float* Wk    = (const float*)d_in[5];
    const float* vvec  = (const float*)d_in[6];

    float* out_aw  = (float*)d_out;                          // (B,Q,K)
    float* out_ctx = out_aw + (size_t)BB * QQ * KK;          // (B,Q,H)

    const int proj_smem = (32 * 128 + 64 * 132) * (int)sizeof(float);  // 50688 B
    cudaFuncSetAttribute(proj_kernel, cudaFuncAttributeMaxDynamicSharedMemorySize, proj_smem);

    proj_kernel<<<320, 256, proj_smem>>>(query, key, Wq, Wk);
    score_kernel<<<BB * (QQ / QT) * KS, 256>>>(mask, vvec, out_aw);
    softmax_kernel<<<BB * QQ / 4, 128>>>(out_aw);
    ctx_kernel<<<BB * (QQ / CQT) * CKS, 256>>>(value, out_aw);
    ctx_reduce_kernel<<<BB * QQ * HH / 256, 256>>>(out_ctx);
}

// round 11
// speedup vs baseline: 1.3917x; 1.0428x over previous
#include <cuda_runtime.h>
#include <cuda_bf16.h>
#include <cuda_fp16.h>
#include <cstdint>
#include <cstring>

// Problem constants (B=4, Q=256, K=1024, H=128)
#define BB 4
#define QQ 256
#define KK 1024
#define HH 128
#define QT 4             // queries per score block
#define KS 8             // k-splits per query row (score)
#define KCH (KK / KS)    // 128 k-rows per score block
#define T2 32            // k-rows per stage tile
#define PITCHB 272       // bytes per smem tile row (256 data + 16 pad)
#define TILEB (T2 * PITCHB)  // 8704 bytes per buffer
#define CKS 16           // ctx k-splits
#define CKCH (KK / CKS)  // 64 k per ctx block
#define CQT 32           // ctx queries per block
#define CT 32            // ctx k-rows per stage tile

// Scratch (device globals — no allocation allowed)
__device__ __half g_qp[BB * QQ * HH];          // 256 KB
__device__ __half g_kp[BB * KK * HH];          // 1 MB
__device__ float  g_cpart[CKS * BB * QQ * HH]; // 8 MB ctx partials

__device__ __forceinline__ uint32_t h2u(__half2 h) { uint32_t u; memcpy(&u, &h, 4); return u; }
__device__ __forceinline__ __half2 u2h(uint32_t u) { __half2 h; memcpy(&h, &u, 4); return h; }

__device__ __forceinline__ uint32_t htanh2(uint32_t a) {
    uint32_t r;
    asm("tanh.approx.f16x2 %0, %1;" : "=r"(r) : "r"(a));
    return r;
}

__device__ __forceinline__ void cp_async16(void* dst, const void* src) {
    uint32_t d = (uint32_t)__cvta_generic_to_shared(dst);
    asm volatile("cp.async.ca.shared.global [%0], [%1], 16;\n" :: "r"(d), "l"(src));
}

// ---------------- Projection GEMM: out[row][h] = sum_d in[row][d] * W[h][d]
__global__ __launch_bounds__(256, 2) void proj_kernel(
    const float* __restrict__ query, const float* __restrict__ key,
    const float* __restrict__ Wq, const float* __restrict__ Wk) {
    extern __shared__ float psm[];
    float4* s_a = (float4*)psm;                   // [32][32] float4, pitch 32
    float4* s_b = (float4*)(psm + 32 * 128);      // [64][33] float4, pitch 33

    int bx = blockIdx.x;
    const float* in; const float* W; __half* out;
    int rowTile, hTile;
    if (bx < 64) { in = query; W = Wq; out = g_qp; rowTile = (bx >> 1) * 32; hTile = (bx & 1) * 64; }
    else { bx -= 64; in = key; W = Wk; out = g_kp; rowTile = (bx >> 1) * 32; hTile = (bx & 1) * 64; }

    const int tid = threadIdx.x;
    const int tx = tid & 15;
    const int ty = tid >> 4;

    {
        const float4* in4 = (const float4*)(in + (size_t)rowTile * HH);
        const float4* w4 = (const float4*)(W + (size_t)hTile * HH);
        int idx = tid;
#pragma unroll
        for (int i = 0; i < 4; ++i, idx += 256) {
            int r = idx >> 5, c = idx & 31;
            s_a[r * 32 + c] = in4[r * 32 + c];
        }
        idx = tid;
#pragma unroll
        for (int i = 0; i < 8; ++i, idx += 256) {
            int r = idx >> 5, c = idx & 31;
            s_b[r * 33 + c] = w4[r * 32 + c];
        }
    }
    __syncthreads();

    float acc[2][4] = {};
#pragma unroll
    for (int s = 0; s < 32; ++s) {
        float4 a[2], b[4];
#pragma unroll
        for (int i = 0; i < 2; ++i) a[i] = s_a[(ty + 16 * i) * 32 + s];
#pragma unroll
        for (int j = 0; j < 4; ++j) b[j] = s_b[(tx + 16 * j) * 33 + s];
#pragma unroll
        for (int i = 0; i < 2; ++i)
#pragma unroll
            for (int j = 0; j < 4; ++j)
                acc[i][j] += a[i].x * b[j].x + a[i].y * b[j].y
                           + a[i].z * b[j].z + a[i].w * b[j].w;
    }

#pragma unroll
    for (int i = 0; i < 2; ++i)
#pragma unroll
        for (int j = 0; j < 4; ++j)
            out[(size_t)(rowTile + ty + 16 * i) * HH + hTile + tx + 16 * j] =
                __float2half(acc[i][j]);
}

// ---------------- Score kernel: HMMA over tanh(qp+kp) features. (unchanged)
__global__ __launch_bounds__(256, 3) void score_kernel(const int* __restrict__ mask,
                                                       const float* __restrict__ vvec,
                                                       float* __restrict__ out_aw) {
    __shared__ __align__(16) unsigned char s_kp[2][TILEB];

    const int tid = threadIdx.x;
    const int bx = blockIdx.x;
    const int b = bx >> 9;
    const int qt = (bx >> 3) & 63;
    const int ks = bx & 7;
    const int q0 = qt * QT;
    const int kbase = ks * KCH;
    const int warp = tid >> 5;
    const int lane = tid & 31;
    const int q = warp & 3;
    const int kh = warp >> 2;
    const int t4 = lane & 3;
    const int grp = lane >> 2;

    uint32_t qf[16], vf[16];
    {
        const __half2* qrow = (const __half2*)(g_qp + (size_t)(b * QQ + q0 + q) * HH);
#pragma unroll
        for (int c = 0; c < 8; ++c) {
            qf[2 * c]     = h2u(qrow[8 * c + t4]);
            qf[2 * c + 1] = h2u(qrow[8 * c + t4 + 4]);
            vf[2 * c]     = h2u(__floats2half2_rn(vvec[16 * c + 2 * t4],
                                                  vvec[16 * c + 2 * t4 + 1]));
            vf[2 * c + 1] = h2u(__floats2half2_rn(vvec[16 * c + 2 * t4 + 8],
                                                  vvec[16 * c + 2 * t4 + 9]));
        }
    }

    const int bq = b * QQ + q0 + q;
    const int* mrow = mask + (size_t)bq * KK;
    float* aw = out_aw + (size_t)bq * KK;

    const char* kp_src = (const char*)(g_kp + ((size_t)b * KK + kbase) * HH);

    auto stage = [&](int t, int buf) {
        const char* src = kp_src + (size_t)t * T2 * 256;
        unsigned char* dst = &s_kp[buf][0];
#pragma unroll
        for (int i = 0; i < 2; ++i) {
            int c = tid + i * 256;
            int r = c >> 4, col = c & 15;
            cp_async16(dst + r * PITCHB + col * 16, src + c * 16);
        }
        asm volatile("cp.async.commit_group;\n");
    };

    uint32_t sbase = (uint32_t)__cvta_generic_to_shared(&s_kp[0][0]);
    const int lrow = kh * 16 + ((lane >> 3) & 1) * 8 + (lane & 7);
    const uint32_t laddr0 = sbase + (uint32_t)lrow * PITCHB + ((lane >> 4) ? 16u : 0u);

    stage(0, 0);
    for (int tt = 0; tt < KCH / T2; ++tt) {
        const int buf = tt & 1;
        if (tt < KCH / T2 - 1) {
            stage(tt + 1, buf ^ 1);
            asm volatile("cp.async.wait_group 1;\n");
        } else {
            asm volatile("cp.async.wait_group 0;\n");
        }
        __syncthreads();

        const uint32_t maddr = laddr0 + (uint32_t)buf * TILEB;
        float f0 = 0.f, f1 = 0.f, f2 = 0.f, f3 = 0.f;
#pragma unroll
        for (int c = 0; c < 8; ++c) {
            uint32_t a0, a1, a2, a3;
            asm volatile("ldmatrix.sync.aligned.m8n8.x4.shared.b16 {%0,%1,%2,%3}, [%4];"
                         : "=r"(a0), "=r"(a1), "=r"(a2), "=r"(a3)
                         : "r"(maddr + 32u * c));
            a0 = htanh2(h2u(__hadd2(u2h(a0), u2h(qf[2 * c]))));
            a1 = htanh2(h2u(__hadd2(u2h(a1), u2h(qf[2 * c]))));
            a2 = htanh2(h2u(__hadd2(u2h(a2), u2h(qf[2 * c + 1]))));
            a3 = htanh2(h2u(__hadd2(u2h(a3), u2h(qf[2 * c + 1]))));
            asm volatile("mma.sync.aligned.m16n8k16.row.col.f32.f16.f16.f32 "
                         "{%0,%1,%2,%3}, {%4,%5,%6,%7}, {%8,%9}, {%0,%1,%2,%3};"
                         : "+f"(f0), "+f"(f1), "+f"(f2), "+f"(f3)
                         : "r"(a0), "r"(a1), "r"(a2), "r"(a3),
                           "r"(vf[2 * c]), "r"(vf[2 * c + 1]));
        }
        if (t4 == 0) {
            int k0 = kbase + tt * T2 + kh * 16 + grp;
            int k1 = k0 + 8;
            // faithful to source: NEG_MASK_SCALE = -1e-09
            aw[k0] = f0 + (-1e-9f) * (1.0f - (float)mrow[k0]);
            aw[k1] = f2 + (-1e-9f) * (1.0f - (float)mrow[k1]);
        }
        __syncthreads();
    }
}

// ---------------- Softmax in-place on out_aw. Warp per row; grid 256 x 128 thr.
__global__ __launch_bounds__(128) void softmax_kernel(float* __restrict__ out_aw) {
    const int warp = threadIdx.x >> 5;
    const int lane = threadIdx.x & 31;
    const int bq = blockIdx.x * 4 + warp;

    float* aw = out_aw + (size_t)bq * KK;
    float vals[32];
    float mx = -1e30f;
#pragma unroll
    for (int j = 0; j < 32; ++j) {
        float s = aw[lane + j * 32];
        vals[j] = s;
        mx = fmaxf(mx, s);
    }
#pragma unroll
    for (int o = 16; o; o >>= 1) mx = fmaxf(mx, __shfl_xor_sync(~0u, mx, o));
    float sum = 0.f;
#pragma unroll
    for (int j = 0; j < 32; ++j) { float e = __expf(vals[j] - mx); vals[j] = e; sum += e; }
#pragma unroll
    for (int o = 16; o; o >>= 1) sum += __shfl_xor_sync(~0u, sum, o);
    float inv = 1.0f / sum;
#pragma unroll
    for (int j = 0; j < 32; ++j) aw[lane + j * 32] = vals[j] * inv;
}

// ---------------- Context partial GEMM: 32q x 128h x 64k per block, smem-staged value.
// grid 512: bx = ((b*8+qt)*16+ks). Thread: h4 = tid&31 (float4 h-slice),
// qs = tid>>5 -> 4 queries qs*4..qs*4+3. Value tiles via cp.async double buffer.
__global__ __launch_bounds__(256) void ctx_kernel(const float* __restrict__ value,
                                                  const float* __restrict__ out_aw) {
    __shared__ float s_w[CQT * CKCH];        // 8 KB
    __shared__ __align__(16) float s_v[2][CT * HH];  // 32 KB

    const int tid = threadIdx.x;
    const int bx = blockIdx.x;
    const int b = bx >> 7;
    const int qt = (bx >> 4) & 7;
    const int ks = bx & 15;
    const int q0 = qt * CQT;
    const int kbase = ks * CKCH;

    const float* vsrc = value + ((size_t)b * KK + kbase) * HH;

    auto stage = [&](int t, int buf) {
        const float4* src = (const float4*)(vsrc + (size_t)t * CT * HH);
        float4* dst = (float4*)&s_v[buf][0];
#pragma unroll
        for (int i = 0; i < 4; ++i) {
            int idx = tid + i * 256;   // 0..1023
            cp_async16(dst + idx, src + idx);
        }
        asm volatile("cp.async.commit_group;\n");
    };

    stage(0, 0);

    // stage weights: 32 rows x 16 float4 = 512 float4, 2/thread
    {
        int idx = tid;
#pragma unroll
        for (int i = 0; i < 2; ++i, idx += 256) {
            int r = idx >> 4, c = idx & 15;
            ((float4*)s_w)[idx] =
                ((const float4*)(out_aw + (size_t)(b * QQ + q0 + r) * KK + kbase))[c];
        }
    }

    const int h4 = tid & 31;
    const int qs = tid >> 5;
    const float* w0 = s_w + (qs * 4 + 0) * CKCH;
    const float* w1 = s_w + (qs * 4 + 1) * CKCH;
    const float* w2 = s_w + (qs * 4 + 2) * CKCH;
    const float* w3 = s_w + (qs * 4 + 3) * CKCH;

    float4 A0 = {0,0,0,0}, A1 = {0,0,0,0}, A2 = {0,0,0,0}, A3 = {0,0,0,0};

    for (int t = 0; t < CKCH / CT; ++t) {
        const int buf = t & 1;
        if (t < CKCH / CT - 1) {
            stage(t + 1, buf ^ 1);
            asm volatile("cp.async.wait_group 1;\n");
        } else {
            asm volatile("cp.async.wait_group 0;\n");
        }
        __syncthreads();

        const float4* vt = (const float4*)&s_v[buf][0] + h4;
        const int kb = t * CT;
#pragma unroll 4
        for (int k = 0; k < CT; ++k) {
            float4 v = vt[k * 32];
            float a = w0[kb + k], c = w1[kb + k], d = w2[kb + k], e = w3[kb + k];
            A0.x += a * v.x; A0.y += a * v.y; A0.z += a * v.z; A0.w += a * v.w;
            A1.x += c * v.x; A1.y += c * v.y; A1.z += c * v.z; A1.w += c * v.w;
            A2.x += d * v.x; A2.y += d * v.y; A2.z += d * v.z; A2.w += d * v.w;
            A3.x += e * v.x; A3.y += e * v.y; A3.z += e * v.z; A3.w += e * v.w;
        }
        __syncthreads();   // buffer `buf` restaged next iteration
    }

    float* dst = g_cpart + (size_t)ks * (BB * QQ * HH)
               + (size_t)(b * QQ + q0 + qs * 4) * HH;
    ((float4*)dst)[h4] = A0;
    ((float4*)(dst + HH))[h4] = A1;
    ((float4*)(dst + 2 * HH))[h4] = A2;
    ((float4*)(dst + 3 * HH))[h4] = A3;
}

// ---------------- Reduce ctx partials (16-way). grid 512 x 256.
__global__ __launch_bounds__(256) void ctx_reduce_kernel(float* __restrict__ out_ctx) {
    int i = blockIdx.x * 256 + threadIdx.x;   // 0 .. 131071
    const int N = BB * QQ * HH;
    float s = 0.f;
#pragma unroll
    for (int p = 0; p < CKS; ++p) s += g_cpart[p * N + i];
    out_ctx[i] = s;
}

extern "C" void kernel_launch(void* const* d_in, const int* in_sizes, int n_in,
                              void* d_out, int out_size) {
    // metadata order: query, key, value, mask, Wq, Wk, v
    const float* query = (const float*)d_in[0];
    const float* key   = (const float*)d_in[1];
    const float* value = (const float*)d_in[2];
    const int*   mask  = (const int*)d_in[3];
    const float* Wq    = (const float*)d_in[4];
    const float* Wk    = (const float*)d_in[5];
    const float* vvec  = (const float*)d_in[6];

    float* out_aw  = (float*)d_out;                          // (B,Q,K)
    float* out_ctx = out_aw + (size_t)BB * QQ * KK;          // (B,Q,H)

    const int proj_smem = (32 * 128 + 64 * 132) * (int)sizeof(float);  // 50688 B
    cudaFuncSetAttribute(proj_kernel, cudaFuncAttributeMaxDynamicSharedMemorySize, proj_smem);

    proj_kernel<<<320, 256, proj_smem>>>(query, key, Wq, Wk);
    score_kernel<<<BB * (QQ / QT) * KS, 256>>>(mask, vvec, out_aw);
    softmax_kernel<<<BB * QQ / 4, 128>>>(out_aw);
    ctx_kernel<<<BB * (QQ / CQT) * CKS, 256>>>(value, out_aw);
    ctx_reduce_kernel<<<BB * QQ * HH / 256, 256>>>(out_ctx);
}

// round 12
// speedup vs baseline: 1.4225x; 1.0221x over previous
#include <cuda_runtime.h>
#include <cuda_bf16.h>
#include <cuda_fp16.h>
#include <cstdint>
#include <cstring>

// Problem constants (B=4, Q=256, K=1024, H=128)
#define BB 4
#define QQ 256
#define HH 128
#define KK 1024
#define QT 4             // queries per score block
#define KS 16            // k-splits per query row (score)
#define KCH (KK / KS)    // 64 k-rows per score block (= 2 tiles)
#define T2 32            // k-rows per stage tile
#define PITCHB 272       // bytes per smem tile row (256 data + 16 pad)
#define TILEB (T2 * PITCHB)  // 8704 bytes per buffer
#define CKS 16           // ctx k-splits
#define CKCH (KK / CKS)  // 64 k per ctx block
#define CQT 32           // ctx queries per block
#define CT 32            // ctx k-rows per stage tile

// Scratch (device globals — no allocation allowed)
__device__ __half g_qp[BB * QQ * HH];          // 256 KB
__device__ __half g_kp[BB * KK * HH];          // 1 MB
__device__ float  g_cpart[CKS * BB * QQ * HH]; // 8 MB ctx partials

__device__ __forceinline__ uint32_t h2u(__half2 h) { uint32_t u; memcpy(&u, &h, 4); return u; }
__device__ __forceinline__ __half2 u2h(uint32_t u) { __half2 h; memcpy(&h, &u, 4); return h; }

__device__ __forceinline__ uint32_t htanh2(uint32_t a) {
    uint32_t r;
    asm("tanh.approx.f16x2 %0, %1;" : "=r"(r) : "r"(a));
    return r;
}

__device__ __forceinline__ void cp_async16(void* dst, const void* src) {
    uint32_t d = (uint32_t)__cvta_generic_to_shared(dst);
    asm volatile("cp.async.ca.shared.global [%0], [%1], 16;\n" :: "r"(d), "l"(src));
}

// ---------------- Projection GEMM: out[row][h] = sum_d in[row][d] * W[h][d]
__global__ __launch_bounds__(256, 2) void proj_kernel(
    const float* __restrict__ query, const float* __restrict__ key,
    const float* __restrict__ Wq, const float* __restrict__ Wk) {
    extern __shared__ float psm[];
    float4* s_a = (float4*)psm;                   // [32][32] float4, pitch 32
    float4* s_b = (float4*)(psm + 32 * 128);      // [64][33] float4, pitch 33

    int bx = blockIdx.x;
    const float* in; const float* W; __half* out;
    int rowTile, hTile;
    if (bx < 64) { in = query; W = Wq; out = g_qp; rowTile = (bx >> 1) * 32; hTile = (bx & 1) * 64; }
    else { bx -= 64; in = key; W = Wk; out = g_kp; rowTile = (bx >> 1) * 32; hTile = (bx & 1) * 64; }

    const int tid = threadIdx.x;
    const int tx = tid & 15;
    const int ty = tid >> 4;

    {
        const float4* in4 = (const float4*)(in + (size_t)rowTile * HH);
        const float4* w4 = (const float4*)(W + (size_t)hTile * HH);
        int idx = tid;
#pragma unroll
        for (int i = 0; i < 4; ++i, idx += 256) {
            int r = idx >> 5, c = idx & 31;
            s_a[r * 32 + c] = in4[r * 32 + c];
        }
        idx = tid;
#pragma unroll
        for (int i = 0; i < 8; ++i, idx += 256) {
            int r = idx >> 5, c = idx & 31;
            s_b[r * 33 + c] = w4[r * 32 + c];
        }
    }
    __syncthreads();

    float acc[2][4] = {};
#pragma unroll
    for (int s = 0; s < 32; ++s) {
        float4 a[2], b[4];
#pragma unroll
        for (int i = 0; i < 2; ++i) a[i] = s_a[(ty + 16 * i) * 32 + s];
#pragma unroll
        for (int j = 0; j < 4; ++j) b[j] = s_b[(tx + 16 * j) * 33 + s];
#pragma unroll
        for (int i = 0; i < 2; ++i)
#pragma unroll
            for (int j = 0; j < 4; ++j)
                acc[i][j] += a[i].x * b[j].x + a[i].y * b[j].y
                           + a[i].z * b[j].z + a[i].w * b[j].w;
    }

#pragma unroll
    for (int i = 0; i < 2; ++i)
#pragma unroll
        for (int j = 0; j < 4; ++j)
            out[(size_t)(rowTile + ty + 16 * i) * HH + hTile + tx + 16 * j] =
                __float2half(acc[i][j]);
}

// ---------------- Score kernel: HMMA over tanh(qp+kp) features.
// grid 4096: bx = ((b*64)+qt)*16+ks. KCH=64 = 2 tiles, both staged up-front;
// ONE barrier per block, then uninterrupted compute. Split MMA accum chains.
__global__ __launch_bounds__(256, 4) void score_kernel(const int* __restrict__ mask,
                                                       const float* __restrict__ vvec,
                                                       float* __restrict__ out_aw) {
    __shared__ __align__(16) unsigned char s_kp[2][TILEB];

    const int tid = threadIdx.x;
    const int bx = blockIdx.x;
    const int b = bx >> 10;
    const int qt = (bx >> 4) & 63;
    const int ks = bx & 15;
    const int q0 = qt * QT;
    const int kbase = ks * KCH;
    const int warp = tid >> 5;
    const int lane = tid & 31;
    const int q = warp & 3;
    const int kh = warp >> 2;
    const int t4 = lane & 3;
    const int grp = lane >> 2;

    // ---- stage BOTH tiles up-front (single commit)
    {
        const char* kp_src = (const char*)(g_kp + ((size_t)b * KK + kbase) * HH);
#pragma unroll
        for (int t = 0; t < 2; ++t) {
            const char* src = kp_src + (size_t)t * T2 * 256;
            unsigned char* dst = &s_kp[t][0];
#pragma unroll
            for (int i = 0; i < 2; ++i) {
                int c = tid + i * 256;               // 0..511 16B chunks
                int r = c >> 4, col = c & 15;
                cp_async16(dst + r * PITCHB + col * 16, src + c * 16);
            }
        }
        asm volatile("cp.async.commit_group;\n");
    }

    uint32_t qf[16], vf[16];
    {
        const __half2* qrow = (const __half2*)(g_qp + (size_t)(b * QQ + q0 + q) * HH);
#pragma unroll
        for (int c = 0; c < 8; ++c) {
            qf[2 * c]     = h2u(qrow[8 * c + t4]);
            qf[2 * c + 1] = h2u(qrow[8 * c + t4 + 4]);
            vf[2 * c]     = h2u(__floats2half2_rn(vvec[16 * c + 2 * t4],
                                                  vvec[16 * c + 2 * t4 + 1]));
            vf[2 * c + 1] = h2u(__floats2half2_rn(vvec[16 * c + 2 * t4 + 8],
                                                  vvec[16 * c + 2 * t4 + 9]));
        }
    }

    const int bq = b * QQ + q0 + q;
    const int* mrow = mask + (size_t)bq * KK;
    float* aw = out_aw + (size_t)bq * KK;

    uint32_t sbase = (uint32_t)__cvta_generic_to_shared(&s_kp[0][0]);
    const int lrow = kh * 16 + ((lane >> 3) & 1) * 8 + (lane & 7);
    const uint32_t laddr0 = sbase + (uint32_t)lrow * PITCHB + ((lane >> 4) ? 16u : 0u);

    asm volatile("cp.async.wait_group 0;\n");
    __syncthreads();   // the only barrier in this kernel

#pragma unroll
    for (int t = 0; t < 2; ++t) {
        const uint32_t maddr = laddr0 + (uint32_t)t * TILEB;
        float fA0 = 0.f, fA1 = 0.f, fA2 = 0.f, fA3 = 0.f;   // even chunks
        float fB0 = 0.f, fB1 = 0.f, fB2 = 0.f, fB3 = 0.f;   // odd chunks
#pragma unroll
        for (int c = 0; c < 8; c += 2) {
            uint32_t a0, a1, a2, a3, b0, b1, b2, b3;
            asm volatile("ldmatrix.sync.aligned.m8n8.x4.shared.b16 {%0,%1,%2,%3}, [%4];"
                         : "=r"(a0), "=r"(a1), "=r"(a2), "=r"(a3)
                         : "r"(maddr + 32u * c));
            asm volatile("ldmatrix.sync.aligned.m8n8.x4.shared.b16 {%0,%1,%2,%3}, [%4];"
                         : "=r"(b0), "=r"(b1), "=r"(b2), "=r"(b3)
                         : "r"(maddr + 32u * (c + 1)));
            a0 = htanh2(h2u(__hadd2(u2h(a0), u2h(qf[2 * c]))));
            a1 = htanh2(h2u(__hadd2(u2h(a1), u2h(qf[2 * c]))));
            a2 = htanh2(h2u(__hadd2(u2h(a2), u2h(qf[2 * c + 1]))));
            a3 = htanh2(h2u(__hadd2(u2h(a3), u2h(qf[2 * c + 1]))));
            b0 = htanh2(h2u(__hadd2(u2h(b0), u2h(qf[2 * c + 2]))));
            b1 = htanh2(h2u(__hadd2(u2h(b1), u2h(qf[2 * c + 2]))));
            b2 = htanh2(h2u(__hadd2(u2h(b2), u2h(qf[2 * c + 3]))));
            b3 = htanh2(h2u(__hadd2(u2h(b3), u2h(qf[2 * c + 3]))));
            asm volatile("mma.sync.aligned.m16n8k16.row.col.f32.f16.f16.f32 "
                         "{%0,%1,%2,%3}, {%4,%5,%6,%7}, {%8,%9}, {%0,%1,%2,%3};"
                         : "+f"(fA0), "+f"(fA1), "+f"(fA2), "+f"(fA3)
                         : "r"(a0), "r"(a1), "r"(a2), "r"(a3),
                           "r"(vf[2 * c]), "r"(vf[2 * c + 1]));
            asm volatile("mma.sync.aligned.m16n8k16.row.col.f32.f16.f16.f32 "
                         "{%0,%1,%2,%3}, {%4,%5,%6,%7}, {%8,%9}, {%0,%1,%2,%3};"
                         : "+f"(fB0), "+f"(fB1), "+f"(fB2), "+f"(fB3)
                         : "r"(b0), "r"(b1), "r"(b2), "r"(b3),
                           "r"(vf[2 * c + 2]), "r"(vf[2 * c + 3]));
        }
        if (t4 == 0) {
            int k0 = kbase + t * T2 + kh * 16 + grp;
            int k1 = k0 + 8;
            // faithful to source: NEG_MASK_SCALE = -1e-09
            aw[k0] = (fA0 + fB0) + (-1e-9f) * (1.0f - (float)mrow[k0]);
            aw[k1] = (fA2 + fB2) + (-1e-9f) * (1.0f - (float)mrow[k1]);
        }
    }
}

// ---------------- Softmax in-place on out_aw. Warp per row; grid 256 x 128 thr.
__global__ __launch_bounds__(128) void softmax_kernel(float* __restrict__ out_aw) {
    const int warp = threadIdx.x >> 5;
    const int lane = threadIdx.x & 31;
    const int bq = blockIdx.x * 4 + warp;

    float* aw = out_aw + (size_t)bq * KK;
    float vals[32];
    float mx = -1e30f;
#pragma unroll
    for (int j = 0; j < 32; ++j) {
        float s = aw[lane + j * 32];
        vals[j] = s;
        mx = fmaxf(mx, s);
    }
#pragma unroll
    for (int o = 16; o; o >>= 1) mx = fmaxf(mx, __shfl_xor_sync(~0u, mx, o));
    float sum = 0.f;
#pragma unroll
    for (int j = 0; j < 32; ++j) { float e = __expf(vals[j] - mx); vals[j] = e; sum += e; }
#pragma unroll
    for (int o = 16; o; o >>= 1) sum += __shfl_xor_sync(~0u, sum, o);
    float inv = 1.0f / sum;
#pragma unroll
    for (int j = 0; j < 32; ++j) aw[lane + j * 32] = vals[j] * inv;
}

// ---------------- Context partial GEMM: 32q x 128h x 64k per block, smem-staged value.
__global__ __launch_bounds__(256) void ctx_kernel(const float* __restrict__ value,
                                                  const float* __restrict__ out_aw) {
    __shared__ float s_w[CQT * CKCH];        // 8 KB
    __shared__ __align__(16) float s_v[2][CT * HH];  // 32 KB

    const int tid = threadIdx.x;
    const int bx = blockIdx.x;
    const int b = bx >> 7;
    const int qt = (bx >> 4) & 7;
    const int ks = bx & 15;
    const int q0 = qt * CQT;
    const int kbase = ks * CKCH;

    const float* vsrc = value + ((size_t)b * KK + kbase) * HH;

    auto stage = [&](int t, int buf) {
        const float4* src = (const float4*)(vsrc + (size_t)t * CT * HH);
        float4* dst = (float4*)&s_v[buf][0];
#pragma unroll
        for (int i = 0; i < 4; ++i) {
            int idx = tid + i * 256;   // 0..1023
            cp_async16(dst + idx, src + idx);
        }
        asm volatile("cp.async.commit_group;\n");
    };

    stage(0, 0);

    {
        int idx = tid;
#pragma unroll
        for (int i = 0; i < 2; ++i, idx += 256) {
            int r = idx >> 4, c = idx & 15;
            ((float4*)s_w)[idx] =
                ((const float4*)(out_aw + (size_t)(b * QQ + q0 + r) * KK + kbase))[c];
        }
    }

    const int h4 = tid & 31;
    const int qs = tid >> 5;
    const float* w0 = s_w + (qs * 4 + 0) * CKCH;
    const float* w1 = s_w + (qs * 4 + 1) * CKCH;
    const float* w2 = s_w + (qs * 4 + 2) * CKCH;
    const float* w3 = s_w + (qs * 4 + 3) * CKCH;

    float4 A0 = {0,0,0,0}, A1 = {0,0,0,0}, A2 = {0,0,0,0}, A3 = {0,0,0,0};

    for (int t = 0; t < CKCH / CT; ++t) {
        const int buf = t & 1;
        if (t < CKCH / CT - 1) {
            stage(t + 1, buf ^ 1);
            asm volatile("cp.async.wait_group 1;\n");
        } else {
            asm volatile("cp.async.wait_group 0;\n");
        }
        __syncthreads();

        const float4* vt = (const float4*)&s_v[buf][0] + h4;
        const int kb = t * CT;
#pragma unroll 4
        for (int k = 0; k < CT; ++k) {
            float4 v = vt[k * 32];
            float a = w0[kb + k], c = w1[kb + k], d = w2[kb + k], e = w3[kb + k];
            A0.x += a * v.x; A0.y += a * v.y; A0.z += a * v.z; A0.w += a * v.w;
            A1.x += c * v.x; A1.y += c * v.y; A1.z += c * v.z; A1.w += c * v.w;
            A2.x += d * v.x; A2.y += d * v.y; A2.z += d * v.z; A2.w += d * v.w;
            A3.x += e * v.x; A3.y += e * v.y; A3.z += e * v.z; A3.w += e * v.w;
        }
        __syncthreads();
    }

    float* dst = g_cpart + (size_t)ks * (BB * QQ * HH)
               + (size_t)(b * QQ + q0 + qs * 4) * HH;
    ((float4*)dst)[h4] = A0;
    ((float4*)(dst + HH))[h4] = A1;
    ((float4*)(dst + 2 * HH))[h4] = A2;
    ((float4*)(dst + 3 * HH))[h4] = A3;
}

// ---------------- Reduce ctx partials (16-way). grid 512 x 256.
__global__ __launch_bounds__(256) void ctx_reduce_kernel(float* __restrict__ out_ctx) {
    int i = blockIdx.x * 256 + threadIdx.x;   // 0 .. 131071
    const int N = BB * QQ * HH;
    float s = 0.f;
#pragma unroll
    for (int p = 0; p < CKS; ++p) s += g_cpart[p * N + i];
    out_ctx[i] = s;
}

extern "C" void kernel_launch(void* const* d_in, const int* in_sizes, int n_in,
                              void* d_out, int out_size) {
    // metadata order: query, key, value, mask, Wq, Wk, v
    const float* query = (const float*)d_in[0];
    const float* key   = (const float*)d_in[1];
    const float* value = (const float*)d_in[2];
    const int*   mask  = (const int*)d_in[3];
    const float* Wq    = (const float*)d_in[4];
    const float* Wk    = (const float*)d_in[5];
    const float* vvec  = (const float*)d_in[6];

    float* out_aw  = (float*)d_out;                          // (B,Q,K)
    float* out_ctx = out_aw + (size_t)BB * QQ * KK;          // (B,Q,H)

    const int proj_smem = (32 * 128 + 64 * 132) * (int)sizeof(float);  // 50688 B
    cudaFuncSetAttribute(proj_kernel, cudaFuncAttributeMaxDynamicSharedMemorySize, proj_smem);

    proj_kernel<<<320, 256, proj_smem>>>(query, key, Wq, Wk);
    score_kernel<<<BB * (QQ / QT) * KS, 256>>>(mask, vvec, out_aw);
    softmax_kernel<<<BB * QQ / 4, 128>>>(out_aw);
    ctx_kernel<<<BB * (QQ / CQT) * CKS, 256>>>(value, out_aw);
    ctx_reduce_kernel<<<BB * QQ * HH / 256, 256>>>(out_ctx);
}